// round 1
// baseline (speedup 1.0000x reference)
#include <cuda_runtime.h>
#include <cstdint>
#include <cstdio>

// ---------------------------------------------------------------------------
// NodeMLP: x[N,32] -> Linear(32,128) -> graphBN(G=16) -> LeakyReLU(0.01)
//          -> Linear(128,64) -> graphBN -> LeakyReLU -> segment_max into M
// Pipeline:
//   k_detect  : detect int64 vs int32 index width (device-side)
//   k_zero    : zero accumulators / histogram / cursor
//   k_cvt     : convert norm_index & super_index to int32 scratch
//   k_hist    : histogram of super_index
//   k_scan    : exclusive scan -> CSR offsets (single block)
//   k_fill    : CSR fill (perm)
//   k_gemm1   : h1 = x@W1^T + b1 (store raw), accumulate per-graph sum/sumsq
//   k_fin(1)  : per (g,ch) scale/shift for layer1
//   k_gemm2   : normalize+leaky h1 on the fly, h2 = @W2^T + b2 (store raw),
//               accumulate per-graph sum/sumsq for layer2
//   k_fin(2)  : scale/shift for layer2
//   k_pool    : per-superpoint gather-max over normalized+leaky h2 (no atomics)
// ---------------------------------------------------------------------------

constexpr int D0 = 32, D1 = 128, D2 = 64, GG = 16;
constexpr float EPS = 1e-5f;
constexpr float SLOPE = 0.01f;

constexpr size_t N_MAX = 1048576;   // >= 1,000,000
constexpr size_t M_MAX = 65536;     // >= 50,000

// g_acc layout: [0,2048) sum1, [2048,4096) sumsq1, [4096,5120) sum2,
//               [5120,6144) sumsq2, [6144,6160) per-graph count
constexpr int OFF_S1 = 0, OFF_SS1 = 2048, OFF_S2 = 4096, OFF_SS2 = 5120, OFF_CNT = 6144;
constexpr int ACC_TOT = 6160;

__device__ float g_h1[N_MAX * (size_t)D1];   // raw (pre-norm) layer-1 output
__device__ float g_h2[N_MAX * (size_t)D2];   // raw (pre-norm) layer-2 output
__device__ float g_acc[ACC_TOT];
__device__ float g_scale1[GG * D1], g_shift1[GG * D1];
__device__ float g_scale2[GG * D2], g_shift2[GG * D2];
__device__ int   g_ni[N_MAX], g_si[N_MAX], g_perm[N_MAX];
__device__ int   g_segcnt[M_MAX], g_segoff[M_MAX + 1], g_cursor[M_MAX];
__device__ int   g_is64;

// ---------------------------------------------------------------------------
__global__ void k_detect(const void* sidx, int M) {
    // super_index is uniform-random in [0,M). If the array is int32, reading
    // it as int64 combines adjacent pairs -> value >= 2^32 almost surely.
    if (threadIdx.x == 0 && blockIdx.x == 0) {
        const long long* p = (const long long*)sidx;
        int ok64 = 1;
        for (int i = 0; i < 256; i++) {
            unsigned long long v = (unsigned long long)p[i];
            if (v >= (unsigned long long)M) { ok64 = 0; break; }
        }
        g_is64 = ok64;
    }
}

__global__ void k_zero(int M) {
    int i = blockIdx.x * blockDim.x + threadIdx.x;
    if (i < ACC_TOT) g_acc[i] = 0.f;
    if (i < M) { g_segcnt[i] = 0; g_cursor[i] = 0; }
}

__global__ void k_cvt(const void* nidx, const void* sidx, int N) {
    int i = blockIdx.x * blockDim.x + threadIdx.x;
    if (i >= N) return;
    if (g_is64) {
        g_ni[i] = (int)((const long long*)nidx)[i];
        g_si[i] = (int)((const long long*)sidx)[i];
    } else {
        g_ni[i] = ((const int*)nidx)[i];
        g_si[i] = ((const int*)sidx)[i];
    }
}

__global__ void k_hist(int N) {
    int i = blockIdx.x * blockDim.x + threadIdx.x;
    if (i < N) atomicAdd(&g_segcnt[g_si[i]], 1);
}

__global__ void k_scan(int M) {
    __shared__ int buf[1024];
    __shared__ int s_run;
    int tid = threadIdx.x;
    if (tid == 0) s_run = 0;
    __syncthreads();
    for (int base = 0; base < M; base += 4096) {
        int i0 = base + tid * 4;
        int v0 = (i0 + 0 < M) ? g_segcnt[i0 + 0] : 0;
        int v1 = (i0 + 1 < M) ? g_segcnt[i0 + 1] : 0;
        int v2 = (i0 + 2 < M) ? g_segcnt[i0 + 2] : 0;
        int v3 = (i0 + 3 < M) ? g_segcnt[i0 + 3] : 0;
        int t = v0 + v1 + v2 + v3;
        int x = t;
        for (int off = 1; off < 1024; off <<= 1) {
            buf[tid] = x; __syncthreads();
            if (tid >= off) x += buf[tid - off];
            __syncthreads();
        }
        int run = s_run;
        int e = run + x - t;
        if (i0 + 0 < M) g_segoff[i0 + 0] = e;
        if (i0 + 1 < M) g_segoff[i0 + 1] = e + v0;
        if (i0 + 2 < M) g_segoff[i0 + 2] = e + v0 + v1;
        if (i0 + 3 < M) g_segoff[i0 + 3] = e + v0 + v1 + v2;
        buf[tid] = x;
        __syncthreads();
        if (tid == 0) s_run = run + buf[1023];
        __syncthreads();
    }
    if (tid == 0) g_segoff[M] = s_run;
}

__global__ void k_fill(int N) {
    int i = blockIdx.x * blockDim.x + threadIdx.x;
    if (i >= N) return;
    int s = g_si[i];
    int pos = g_segoff[s] + atomicAdd(&g_cursor[s], 1);
    g_perm[pos] = i;
}

// ---------------------------------------------------------------------------
// GEMM1: 128-row x 128-col tile per block, K=32. 256 threads, 8x8 per thread.
__global__ __launch_bounds__(256) void k_gemm1(
    const float* __restrict__ x, const float* __restrict__ W1,
    const float* __restrict__ b1, int N)
{
    __shared__ float sA[32][132];   // [k][row]
    __shared__ float sW[32][132];   // [k][col]
    __shared__ float red[2][128];
    __shared__ int   sg[128];

    const int tid = threadIdx.x;
    const int r0 = blockIdx.x * 128;
    const int nrows = min(128, N - r0);

    for (int i = tid; i < 128 * 32; i += 256) {
        int a = i >> 5, k = i & 31;
        sA[k][a] = (a < nrows) ? x[(size_t)(r0 + a) * D0 + k] : 0.f;
        sW[k][a] = W1[i];
    }
    if (tid < 128) {
        sg[tid] = (tid < nrows) ? g_ni[r0 + tid] : 0;
        red[0][tid] = 0.f; red[1][tid] = 0.f;
    }
    __syncthreads();

    const int g0 = sg[0];
    const bool uniform = (sg[nrows - 1] == g0);

    const int tr = tid >> 4, tc = tid & 15;
    float acc[8][8];
#pragma unroll
    for (int i = 0; i < 8; i++)
#pragma unroll
        for (int j = 0; j < 8; j++) acc[i][j] = 0.f;

#pragma unroll 8
    for (int kk = 0; kk < 32; ++kk) {
        float a[8], b[8];
        float4 t;
        t = *(const float4*)&sA[kk][tr * 8];     a[0]=t.x; a[1]=t.y; a[2]=t.z; a[3]=t.w;
        t = *(const float4*)&sA[kk][tr * 8 + 4]; a[4]=t.x; a[5]=t.y; a[6]=t.z; a[7]=t.w;
        t = *(const float4*)&sW[kk][tc * 8];     b[0]=t.x; b[1]=t.y; b[2]=t.z; b[3]=t.w;
        t = *(const float4*)&sW[kk][tc * 8 + 4]; b[4]=t.x; b[5]=t.y; b[6]=t.z; b[7]=t.w;
#pragma unroll
        for (int i = 0; i < 8; i++)
#pragma unroll
            for (int j = 0; j < 8; j++) acc[i][j] += a[i] * b[j];
    }

    float bias[8];
#pragma unroll
    for (int j = 0; j < 8; j++) bias[j] = __ldg(&b1[tc * 8 + j]);

    float lsum[8], lss[8];
#pragma unroll
    for (int j = 0; j < 8; j++) { lsum[j] = 0.f; lss[j] = 0.f; }

#pragma unroll
    for (int i = 0; i < 8; i++) {
        int row = tr * 8 + i;
        if (row < nrows) {
            float h[8];
#pragma unroll
            for (int j = 0; j < 8; j++) h[j] = acc[i][j] + bias[j];
            if (uniform) {
#pragma unroll
                for (int j = 0; j < 8; j++) { lsum[j] += h[j]; lss[j] += h[j] * h[j]; }
            } else {
                int g = sg[row];
#pragma unroll
                for (int j = 0; j < 8; j++) {
                    atomicAdd(&g_acc[OFF_S1 + g * D1 + tc * 8 + j], h[j]);
                    atomicAdd(&g_acc[OFF_SS1 + g * D1 + tc * 8 + j], h[j] * h[j]);
                }
            }
            float4 o0 = make_float4(h[0], h[1], h[2], h[3]);
            float4 o1 = make_float4(h[4], h[5], h[6], h[7]);
            size_t base = (size_t)(r0 + row) * D1 + tc * 8;
            *(float4*)&g_h1[base] = o0;
            *(float4*)&g_h1[base + 4] = o1;
        }
    }

    if (uniform) {
#pragma unroll
        for (int j = 0; j < 8; j++) {
            atomicAdd(&red[0][tc * 8 + j], lsum[j]);
            atomicAdd(&red[1][tc * 8 + j], lss[j]);
        }
        __syncthreads();
        if (tid < 128) {
            atomicAdd(&g_acc[OFF_S1 + g0 * D1 + tid], red[0][tid]);
            atomicAdd(&g_acc[OFF_SS1 + g0 * D1 + tid], red[1][tid]);
        }
        if (tid == 0) atomicAdd(&g_acc[OFF_CNT + g0], (float)nrows);
    } else {
        if (tid < nrows) atomicAdd(&g_acc[OFF_CNT + sg[tid]], 1.0f);
    }
}

// per (g,ch): scale = gamma * rsqrt(var+eps), shift = beta - mean*scale
__global__ void k_fin(const float* __restrict__ gamma, const float* __restrict__ beta, int layer) {
    int D = (layer == 1) ? D1 : D2;
    const float* sum = (layer == 1) ? g_acc + OFF_S1 : g_acc + OFF_S2;
    const float* ss  = (layer == 1) ? g_acc + OFF_SS1 : g_acc + OFF_SS2;
    float* sc = (layer == 1) ? g_scale1 : g_scale2;
    float* sh = (layer == 1) ? g_shift1 : g_shift2;
    int i = blockIdx.x * blockDim.x + threadIdx.x;
    if (i >= GG * D) return;
    int g = i / D, ch = i % D;
    float c = fmaxf(g_acc[OFF_CNT + g], 1.f);
    float m = sum[i] / c;
    float var = fmaxf(ss[i] / c - m * m, 0.f);
    float s = gamma[ch] * rsqrtf(var + EPS);
    sc[i] = s;
    sh[i] = beta[ch] - m * s;
}

// ---------------------------------------------------------------------------
// GEMM2: 128-row x 64-col tile, K=128 in 4 chunks of 32. Normalize+leaky h1
// on the fly during the tile load.
__global__ __launch_bounds__(256) void k_gemm2(
    const float* __restrict__ W2, const float* __restrict__ b2, int N)
{
    __shared__ float sA[32][132];  // [k'][row]
    __shared__ float sW[32][68];   // [k'][col]
    __shared__ float red[2][64];
    __shared__ int   sg[128];

    const int tid = threadIdx.x;
    const int r0 = blockIdx.x * 128;
    const int nrows = min(128, N - r0);

    if (tid < 128) sg[tid] = (tid < nrows) ? g_ni[r0 + tid] : 0;
    if (tid < 64) { red[0][tid] = 0.f; red[1][tid] = 0.f; }

    const int tr = tid >> 4, tc = tid & 15;
    float acc[8][4];
#pragma unroll
    for (int i = 0; i < 8; i++)
#pragma unroll
        for (int j = 0; j < 4; j++) acc[i][j] = 0.f;

    for (int kc = 0; kc < 128; kc += 32) {
        __syncthreads();
        for (int i = tid; i < 128 * 32; i += 256) {
            int row = i >> 5, k = i & 31;
            float v = 0.f;
            if (row < nrows) {
                int ch = kc + k;
                int g = sg[row];
                float t = g_h1[(size_t)(r0 + row) * D1 + ch];
                t = t * g_scale1[g * D1 + ch] + g_shift1[g * D1 + ch];
                v = fmaxf(t, SLOPE * t);
            }
            sA[k][row] = v;
        }
        for (int i = tid; i < 64 * 32; i += 256) {
            int col = i >> 5, k = i & 31;
            sW[k][col] = W2[(size_t)col * D1 + kc + k];
        }
        __syncthreads();
#pragma unroll 8
        for (int kk = 0; kk < 32; ++kk) {
            float a[8], b[4];
            float4 t;
            t = *(const float4*)&sA[kk][tr * 8];     a[0]=t.x; a[1]=t.y; a[2]=t.z; a[3]=t.w;
            t = *(const float4*)&sA[kk][tr * 8 + 4]; a[4]=t.x; a[5]=t.y; a[6]=t.z; a[7]=t.w;
            t = *(const float4*)&sW[kk][tc * 4];     b[0]=t.x; b[1]=t.y; b[2]=t.z; b[3]=t.w;
#pragma unroll
            for (int i = 0; i < 8; i++)
#pragma unroll
                for (int j = 0; j < 4; j++) acc[i][j] += a[i] * b[j];
        }
    }

    const int g0 = sg[0];
    const bool uniform = (sg[nrows - 1] == g0);

    float bias[4];
#pragma unroll
    for (int j = 0; j < 4; j++) bias[j] = __ldg(&b2[tc * 4 + j]);

    float lsum[4], lss[4];
#pragma unroll
    for (int j = 0; j < 4; j++) { lsum[j] = 0.f; lss[j] = 0.f; }

#pragma unroll
    for (int i = 0; i < 8; i++) {
        int row = tr * 8 + i;
        if (row < nrows) {
            float h[4];
#pragma unroll
            for (int j = 0; j < 4; j++) h[j] = acc[i][j] + bias[j];
            if (uniform) {
#pragma unroll
                for (int j = 0; j < 4; j++) { lsum[j] += h[j]; lss[j] += h[j] * h[j]; }
            } else {
                int g = sg[row];
#pragma unroll
                for (int j = 0; j < 4; j++) {
                    atomicAdd(&g_acc[OFF_S2 + g * D2 + tc * 4 + j], h[j]);
                    atomicAdd(&g_acc[OFF_SS2 + g * D2 + tc * 4 + j], h[j] * h[j]);
                }
            }
            *(float4*)&g_h2[(size_t)(r0 + row) * D2 + tc * 4] =
                make_float4(h[0], h[1], h[2], h[3]);
        }
    }

    if (uniform) {
#pragma unroll
        for (int j = 0; j < 4; j++) {
            atomicAdd(&red[0][tc * 4 + j], lsum[j]);
            atomicAdd(&red[1][tc * 4 + j], lss[j]);
        }
        __syncthreads();
        if (tid < 64) {
            atomicAdd(&g_acc[OFF_S2 + g0 * D2 + tid], red[0][tid]);
            atomicAdd(&g_acc[OFF_SS2 + g0 * D2 + tid], red[1][tid]);
        }
    }
    // counts already accumulated in k_gemm1
}

// ---------------------------------------------------------------------------
// Gather-max: one warp per superpoint; lane handles channels (lane, lane+32).
__global__ void k_pool(float* __restrict__ out, int M) {
    int warp = (blockIdx.x * blockDim.x + threadIdx.x) >> 5;
    int lane = threadIdx.x & 31;
    if (warp >= M) return;
    int s = g_segoff[warp], e = g_segoff[warp + 1];
    float m0 = -3.402823466e38f, m1 = -3.402823466e38f;
    for (int j = s; j < e; ++j) {
        int row = g_perm[j];
        int g = g_ni[row];
        size_t base = (size_t)row * D2;
        float v0 = g_h2[base + lane];
        float v1 = g_h2[base + 32 + lane];
        float a0 = v0 * g_scale2[g * D2 + lane] + g_shift2[g * D2 + lane];
        float a1 = v1 * g_scale2[g * D2 + 32 + lane] + g_shift2[g * D2 + 32 + lane];
        a0 = fmaxf(a0, SLOPE * a0);
        a1 = fmaxf(a1, SLOPE * a1);
        m0 = fmaxf(m0, a0);
        m1 = fmaxf(m1, a1);
    }
    if (s == e) { m0 = 0.f; m1 = 0.f; }  // empty segment -> 0 per reference
    out[(size_t)warp * D2 + lane] = m0;
    out[(size_t)warp * D2 + 32 + lane] = m1;
}

// ---------------------------------------------------------------------------
extern "C" void kernel_launch(void* const* d_in, const int* in_sizes, int n_in,
                              void* d_out, int out_size) {
    const float* x     = (const float*)d_in[0];
    const float* W1    = (const float*)d_in[1];
    const float* b1    = (const float*)d_in[2];
    const float* g1    = (const float*)d_in[3];
    const float* beta1 = (const float*)d_in[4];
    const float* W2    = (const float*)d_in[5];
    const float* b2    = (const float*)d_in[6];
    const float* g2    = (const float*)d_in[7];
    const float* beta2 = (const float*)d_in[8];
    const void*  nidx  = d_in[9];
    const void*  sidx  = d_in[10];
    float* out = (float*)d_out;

    int N = in_sizes[0] / D0;
    int M = out_size / D2;

    int zgrid = (max(M, ACC_TOT) + 255) / 256;
    int ngrid = (N + 255) / 256;
    int tgrid = (N + 127) / 128;

    k_detect<<<1, 32>>>(sidx, M);
    k_zero<<<zgrid, 256>>>(M);
    k_cvt<<<ngrid, 256>>>(nidx, sidx, N);
    k_hist<<<ngrid, 256>>>(N);
    k_scan<<<1, 1024>>>(M);
    k_fill<<<ngrid, 256>>>(N);
    k_gemm1<<<tgrid, 256>>>(x, W1, b1, N);
    k_fin<<<(GG * D1 + 255) / 256, 256>>>(g1, beta1, 1);
    k_gemm2<<<tgrid, 256>>>(W2, b2, N);
    k_fin<<<(GG * D2 + 255) / 256, 256>>>(g2, beta2, 2);
    k_pool<<<(M + 7) / 8, 256>>>(out, M);
}

// round 2
// speedup vs baseline: 1.4064x; 1.4064x over previous
#include <cuda_runtime.h>
#include <cstdint>
#include <cstdio>

// ---------------------------------------------------------------------------
// NodeMLP: x[N,32] -> Linear(32,128) -> graphBN(G=16) -> LeakyReLU(0.01)
//          -> Linear(128,64) -> graphBN -> LeakyReLU -> segment_max into M
//
// Round-2 architecture (tensor cores, h1 never hits HBM):
//   CSR build  : detect/zero/cvt/hist/scan/fill   (unchanged from R1)
//   k_stats1   : tf32-MMA GEMM1, accumulate per-graph sum/sumsq of h1 only
//   k_fin(1)   : scale/shift for layer1
//   k_fused    : tf32-MMA GEMM1 again -> normalize+leaky into SMEM ->
//                tf32-MMA GEMM2 from SMEM -> stats2 -> store raw h2
//   k_fin(2)   : scale/shift for layer2
//   k_pool     : per-superpoint gather-max (normalize h2 on the fly)
// ---------------------------------------------------------------------------

constexpr int D0 = 32, D1 = 128, D2 = 64, GG = 16;
constexpr float EPS = 1e-5f;
constexpr float SLOPE = 0.01f;

constexpr size_t N_MAX = 1048576;
constexpr size_t M_MAX = 65536;

constexpr int OFF_S1 = 0, OFF_SS1 = 2048, OFF_S2 = 4096, OFF_SS2 = 5120, OFF_CNT = 6144;
constexpr int ACC_TOT = 6160;

__device__ float g_h2[N_MAX * (size_t)D2];   // raw (pre-norm) layer-2 output
__device__ float g_acc[ACC_TOT];
__device__ float g_scale1[GG * D1], g_shift1[GG * D1];
__device__ float g_scale2[GG * D2], g_shift2[GG * D2];
__device__ int   g_ni[N_MAX], g_si[N_MAX], g_perm[N_MAX];
__device__ int   g_segcnt[M_MAX], g_segoff[M_MAX + 1], g_cursor[M_MAX];
__device__ int   g_is64;

// ---------------------------------------------------------------------------
__device__ __forceinline__ uint32_t f2tf(float f) {
    uint32_t u;
    asm("cvt.rna.tf32.f32 %0, %1;" : "=r"(u) : "f"(f));
    return u;
}

// D += A(16x8,row) * B(8x8,col)   tf32 in, fp32 accum
__device__ __forceinline__ void mma_tf32(float* d, const uint32_t* a, const uint32_t* b) {
    asm volatile(
        "mma.sync.aligned.m16n8k8.row.col.f32.tf32.tf32.f32 "
        "{%0,%1,%2,%3}, {%4,%5,%6,%7}, {%8,%9}, {%0,%1,%2,%3};"
        : "+f"(d[0]), "+f"(d[1]), "+f"(d[2]), "+f"(d[3])
        : "r"(a[0]), "r"(a[1]), "r"(a[2]), "r"(a[3]), "r"(b[0]), "r"(b[1]));
}

// ---------------------------------------------------------------------------
__global__ void k_detect(const void* sidx, int M) {
    if (threadIdx.x == 0 && blockIdx.x == 0) {
        const long long* p = (const long long*)sidx;
        int ok64 = 1;
        for (int i = 0; i < 256; i++) {
            unsigned long long v = (unsigned long long)p[i];
            if (v >= (unsigned long long)M) { ok64 = 0; break; }
        }
        g_is64 = ok64;
    }
}

__global__ void k_zero(int M) {
    int i = blockIdx.x * blockDim.x + threadIdx.x;
    if (i < ACC_TOT) g_acc[i] = 0.f;
    if (i < M) { g_segcnt[i] = 0; g_cursor[i] = 0; }
}

__global__ void k_cvt(const void* nidx, const void* sidx, int N) {
    int i = blockIdx.x * blockDim.x + threadIdx.x;
    if (i >= N) return;
    if (g_is64) {
        g_ni[i] = (int)((const long long*)nidx)[i];
        g_si[i] = (int)((const long long*)sidx)[i];
    } else {
        g_ni[i] = ((const int*)nidx)[i];
        g_si[i] = ((const int*)sidx)[i];
    }
}

__global__ void k_hist(int N) {
    int i = blockIdx.x * blockDim.x + threadIdx.x;
    if (i < N) atomicAdd(&g_segcnt[g_si[i]], 1);
}

__global__ void k_scan(int M) {
    __shared__ int buf[1024];
    __shared__ int s_run;
    int tid = threadIdx.x;
    if (tid == 0) s_run = 0;
    __syncthreads();
    for (int base = 0; base < M; base += 4096) {
        int i0 = base + tid * 4;
        int v0 = (i0 + 0 < M) ? g_segcnt[i0 + 0] : 0;
        int v1 = (i0 + 1 < M) ? g_segcnt[i0 + 1] : 0;
        int v2 = (i0 + 2 < M) ? g_segcnt[i0 + 2] : 0;
        int v3 = (i0 + 3 < M) ? g_segcnt[i0 + 3] : 0;
        int t = v0 + v1 + v2 + v3;
        int x = t;
        for (int off = 1; off < 1024; off <<= 1) {
            buf[tid] = x; __syncthreads();
            if (tid >= off) x += buf[tid - off];
            __syncthreads();
        }
        int run = s_run;
        int e = run + x - t;
        if (i0 + 0 < M) g_segoff[i0 + 0] = e;
        if (i0 + 1 < M) g_segoff[i0 + 1] = e + v0;
        if (i0 + 2 < M) g_segoff[i0 + 2] = e + v0 + v1;
        if (i0 + 3 < M) g_segoff[i0 + 3] = e + v0 + v1 + v2;
        buf[tid] = x;
        __syncthreads();
        if (tid == 0) s_run = run + buf[1023];
        __syncthreads();
    }
    if (tid == 0) g_segoff[M] = s_run;
}

__global__ void k_fill(int N) {
    int i = blockIdx.x * blockDim.x + threadIdx.x;
    if (i >= N) return;
    int s = g_si[i];
    int pos = g_segoff[s] + atomicAdd(&g_cursor[s], 1);
    g_perm[pos] = i;
}

// ---------------------------------------------------------------------------
// Shared GEMM1 fragment math: block = 128 rows x 128 cols, 8 warps (4x2),
// warp tile = 32 rows x 64 cols -> acc[2 mf][8 nf][4].
// sA/sW layout: [k][idx] with stride 136 (conflict-free: 136%32 == 8).

__device__ __forceinline__ void gemm1_mma(
    const uint32_t (*sA)[136], const uint32_t (*sW)[136],
    int lane, int rb0, int cb, float acc[2][8][4])
{
#pragma unroll
    for (int ks = 0; ks < 4; ks++) {
        const int k0 = ks * 8 + (lane & 3);
        uint32_t a[2][4];
#pragma unroll
        for (int mf = 0; mf < 2; mf++) {
            int rb = rb0 + mf * 16 + (lane >> 2);
            a[mf][0] = sA[k0][rb];     a[mf][1] = sA[k0][rb + 8];
            a[mf][2] = sA[k0 + 4][rb]; a[mf][3] = sA[k0 + 4][rb + 8];
        }
#pragma unroll
        for (int nf = 0; nf < 8; nf++) {
            int cn = cb + nf * 8 + (lane >> 2);
            uint32_t b[2];
            b[0] = sW[k0][cn]; b[1] = sW[k0 + 4][cn];
#pragma unroll
            for (int mf = 0; mf < 2; mf++) mma_tf32(acc[mf][nf], a[mf], b);
        }
    }
}

// ---------------------------------------------------------------------------
// Stats pass: GEMM1, accumulate per-graph sum/sumsq of h1 = xW1^T + b1.
__global__ __launch_bounds__(256) void k_stats1(
    const float* __restrict__ x, const float* __restrict__ W1,
    const float* __restrict__ b1, int N)
{
    __shared__ uint32_t sA[32][136];
    __shared__ uint32_t sW[32][136];
    __shared__ float red[2][128];
    __shared__ int sg[128];

    const int tid = threadIdx.x;
    const int r0 = blockIdx.x * 128;
    const int nrows = min(128, N - r0);

    for (int i = tid; i < 128 * 32; i += 256) {
        int r = i >> 5, k = i & 31;
        sA[k][r] = f2tf((r < nrows) ? x[(size_t)r0 * D0 + i] : 0.f);
        sW[k][r] = f2tf(W1[i]);
    }
    if (tid < 128) {
        sg[tid] = (tid < nrows) ? g_ni[r0 + tid] : 0;
        red[0][tid] = 0.f; red[1][tid] = 0.f;
    }
    __syncthreads();

    const int lane = tid & 31, wid = tid >> 5;
    const int rb0 = (wid >> 1) * 32, cb = (wid & 1) * 64;

    float acc[2][8][4];
#pragma unroll
    for (int mf = 0; mf < 2; mf++)
#pragma unroll
        for (int nf = 0; nf < 8; nf++)
#pragma unroll
            for (int q = 0; q < 4; q++) acc[mf][nf][q] = 0.f;

    gemm1_mma(sA, sW, lane, rb0, cb, acc);

    const int g0 = sg[0];
    const bool uniform = (sg[nrows - 1] == g0);

    if (uniform) {
#pragma unroll
        for (int nf = 0; nf < 8; nf++) {
#pragma unroll
            for (int j = 0; j < 2; j++) {
                int c = cb + nf * 8 + 2 * (lane & 3) + j;
                float bias = __ldg(&b1[c]);
                float s = 0.f, ss = 0.f;
#pragma unroll
                for (int mf = 0; mf < 2; mf++) {
                    int r = rb0 + mf * 16 + (lane >> 2);
                    if (r < nrows) { float h = acc[mf][nf][j] + bias; s += h; ss += h * h; }
                    if (r + 8 < nrows) { float h = acc[mf][nf][j + 2] + bias; s += h; ss += h * h; }
                }
#pragma unroll
                for (int off = 4; off < 32; off <<= 1) {
                    s  += __shfl_xor_sync(0xffffffffu, s, off);
                    ss += __shfl_xor_sync(0xffffffffu, ss, off);
                }
                if (lane < 4) { atomicAdd(&red[0][c], s); atomicAdd(&red[1][c], ss); }
            }
        }
        __syncthreads();
        if (tid < 128) {
            atomicAdd(&g_acc[OFF_S1 + g0 * D1 + tid], red[0][tid]);
            atomicAdd(&g_acc[OFF_SS1 + g0 * D1 + tid], red[1][tid]);
        }
        if (tid == 0) atomicAdd(&g_acc[OFF_CNT + g0], (float)nrows);
    } else {
#pragma unroll
        for (int nf = 0; nf < 8; nf++)
#pragma unroll
            for (int j = 0; j < 2; j++) {
                int c = cb + nf * 8 + 2 * (lane & 3) + j;
                float bias = __ldg(&b1[c]);
#pragma unroll
                for (int mf = 0; mf < 2; mf++)
#pragma unroll
                    for (int rr = 0; rr < 2; rr++) {
                        int r = rb0 + mf * 16 + (lane >> 2) + rr * 8;
                        if (r < nrows) {
                            float h = acc[mf][nf][j + 2 * rr] + bias;
                            int g = sg[r];
                            atomicAdd(&g_acc[OFF_S1 + g * D1 + c], h);
                            atomicAdd(&g_acc[OFF_SS1 + g * D1 + c], h * h);
                        }
                    }
            }
        if (tid < nrows) atomicAdd(&g_acc[OFF_CNT + sg[tid]], 1.0f);
    }
}

// per (g,ch): scale = gamma * rsqrt(var+eps), shift = beta - mean*scale
__global__ void k_fin(const float* __restrict__ gamma, const float* __restrict__ beta, int layer) {
    int D = (layer == 1) ? D1 : D2;
    const float* sum = (layer == 1) ? g_acc + OFF_S1 : g_acc + OFF_S2;
    const float* ss  = (layer == 1) ? g_acc + OFF_SS1 : g_acc + OFF_SS2;
    float* sc = (layer == 1) ? g_scale1 : g_scale2;
    float* sh = (layer == 1) ? g_shift1 : g_shift2;
    int i = blockIdx.x * blockDim.x + threadIdx.x;
    if (i >= GG * D) return;
    int g = i / D, ch = i % D;
    float c = fmaxf(g_acc[OFF_CNT + g], 1.f);
    float m = sum[i] / c;
    float var = fmaxf(ss[i] / c - m * m, 0.f);
    float s = gamma[ch] * rsqrtf(var + EPS);
    sc[i] = s;
    sh[i] = beta[ch] - m * s;
}

// ---------------------------------------------------------------------------
// Fused: GEMM1 (recompute) -> normalize+leaky into SMEM -> GEMM2 -> stats2
// -> store raw h2. Dynamic SMEM layout (bytes):
//   [0, 69632)            sH[128][136]  (tf32 normalized h1, [k][row])
//   [69632, 69632+36864)  phase1: sA[32][136] + sW1[32][136]; later sW2[128][72]
//   then red2[2][64], sg[128]
constexpr int SH_BYTES   = 128 * 136 * 4;          // 69632
constexpr int PH1_BYTES  = 128 * 72 * 4;           // 36864 (>= 2*32*136*4=34816)
constexpr int FUSED_SMEM = SH_BYTES + PH1_BYTES + 2 * 64 * 4 + 128 * 4;  // 107136

__global__ __launch_bounds__(256) void k_fused(
    const float* __restrict__ x, const float* __restrict__ W1,
    const float* __restrict__ b1, const float* __restrict__ W2,
    const float* __restrict__ b2, int N)
{
    extern __shared__ unsigned char dsm[];
    uint32_t (*sH)[136]  = (uint32_t(*)[136])dsm;
    uint32_t (*sA)[136]  = (uint32_t(*)[136])(dsm + SH_BYTES);
    uint32_t (*sW1)[136] = (uint32_t(*)[136])(dsm + SH_BYTES + 32 * 136 * 4);
    uint32_t (*sW2)[72]  = (uint32_t(*)[72]) (dsm + SH_BYTES);
    float* red2 = (float*)(dsm + SH_BYTES + PH1_BYTES);   // [2][64]
    int*   sg   = (int*)(red2 + 128);

    const int tid = threadIdx.x;
    const int r0 = blockIdx.x * 128;
    const int nrows = min(128, N - r0);

    for (int i = tid; i < 128 * 32; i += 256) {
        int r = i >> 5, k = i & 31;
        sA[k][r]  = f2tf((r < nrows) ? x[(size_t)r0 * D0 + i] : 0.f);
        sW1[k][r] = f2tf(W1[i]);
    }
    if (tid < 128) sg[tid] = (tid < nrows) ? g_ni[r0 + tid] : 0;
    if (tid < 128) { red2[tid] = 0.f; }   // zero red2[2][64]
    __syncthreads();

    const int lane = tid & 31, wid = tid >> 5;
    const int rb0 = (wid >> 1) * 32, cb = (wid & 1) * 64;

    float acc[2][8][4];
#pragma unroll
    for (int mf = 0; mf < 2; mf++)
#pragma unroll
        for (int nf = 0; nf < 8; nf++)
#pragma unroll
            for (int q = 0; q < 4; q++) acc[mf][nf][q] = 0.f;

    gemm1_mma(sA, sW1, lane, rb0, cb, acc);
    __syncthreads();   // done reading sA/sW1 -> region may be overwritten

    // normalize + leaky -> sH (tf32), rows >= nrows get finite garbage (masked later)
#pragma unroll
    for (int nf = 0; nf < 8; nf++) {
#pragma unroll
        for (int j = 0; j < 2; j++) {
            int c = cb + nf * 8 + 2 * (lane & 3) + j;
            float bias = __ldg(&b1[c]);
#pragma unroll
            for (int mf = 0; mf < 2; mf++)
#pragma unroll
                for (int rr = 0; rr < 2; rr++) {
                    int r = rb0 + mf * 16 + (lane >> 2) + rr * 8;
                    float h = acc[mf][nf][j + 2 * rr] + bias;
                    int g = sg[r];
                    float t = h * g_scale1[g * D1 + c] + g_shift1[g * D1 + c];
                    t = fmaxf(t, SLOPE * t);
                    sH[c][r] = f2tf(t);
                }
        }
    }

    // load W2 [64,128] row-major into sW2[k][n]
    for (int i = tid; i < 64 * 128; i += 256) {
        int n = i >> 7, k = i & 127;
        sW2[k][n] = f2tf(W2[i]);
    }
    __syncthreads();

    // GEMM2: warp tile 32 rows x 32 cols, K=128 (16 k-steps)
    const int cb2 = (wid & 1) * 32;
    float acc2[2][4][4];
#pragma unroll
    for (int mf = 0; mf < 2; mf++)
#pragma unroll
        for (int nf = 0; nf < 4; nf++)
#pragma unroll
            for (int q = 0; q < 4; q++) acc2[mf][nf][q] = 0.f;

#pragma unroll
    for (int ks = 0; ks < 16; ks++) {
        const int k0 = ks * 8 + (lane & 3);
        uint32_t a[2][4];
#pragma unroll
        for (int mf = 0; mf < 2; mf++) {
            int rb = rb0 + mf * 16 + (lane >> 2);
            a[mf][0] = sH[k0][rb];     a[mf][1] = sH[k0][rb + 8];
            a[mf][2] = sH[k0 + 4][rb]; a[mf][3] = sH[k0 + 4][rb + 8];
        }
#pragma unroll
        for (int nf = 0; nf < 4; nf++) {
            int cn = cb2 + nf * 8 + (lane >> 2);
            uint32_t b[2];
            b[0] = sW2[k0][cn]; b[1] = sW2[k0 + 4][cn];
#pragma unroll
            for (int mf = 0; mf < 2; mf++) mma_tf32(acc2[mf][nf], a[mf], b);
        }
    }

    const int g0 = sg[0];
    const bool uniform = (sg[nrows - 1] == g0);

    // epilogue: bias, stats2, store raw h2 (float2 per (r, c-pair))
#pragma unroll
    for (int nf = 0; nf < 4; nf++) {
        int cpair = cb2 + nf * 8 + 2 * (lane & 3);
        float bias0 = __ldg(&b2[cpair]);
        float bias1 = __ldg(&b2[cpair + 1]);
        float s0 = 0.f, ss0 = 0.f, s1 = 0.f, ss1 = 0.f;
#pragma unroll
        for (int mf = 0; mf < 2; mf++)
#pragma unroll
            for (int rr = 0; rr < 2; rr++) {
                int r = rb0 + mf * 16 + (lane >> 2) + rr * 8;
                float h0 = acc2[mf][nf][2 * rr] + bias0;
                float h1v = acc2[mf][nf][2 * rr + 1] + bias1;
                if (r < nrows) {
                    if (uniform) {
                        s0 += h0; ss0 += h0 * h0; s1 += h1v; ss1 += h1v * h1v;
                    } else {
                        int g = sg[r];
                        atomicAdd(&g_acc[OFF_S2 + g * D2 + cpair], h0);
                        atomicAdd(&g_acc[OFF_SS2 + g * D2 + cpair], h0 * h0);
                        atomicAdd(&g_acc[OFF_S2 + g * D2 + cpair + 1], h1v);
                        atomicAdd(&g_acc[OFF_SS2 + g * D2 + cpair + 1], h1v * h1v);
                    }
                    float2 v = make_float2(h0, h1v);
                    *(float2*)&g_h2[(size_t)(r0 + r) * D2 + cpair] = v;
                }
            }
        if (uniform) {
#pragma unroll
            for (int off = 4; off < 32; off <<= 1) {
                s0  += __shfl_xor_sync(0xffffffffu, s0, off);
                ss0 += __shfl_xor_sync(0xffffffffu, ss0, off);
                s1  += __shfl_xor_sync(0xffffffffu, s1, off);
                ss1 += __shfl_xor_sync(0xffffffffu, ss1, off);
            }
            if (lane < 4) {
                atomicAdd(&red2[cpair], s0);
                atomicAdd(&red2[cpair + 1], s1);
                atomicAdd(&red2[64 + cpair], ss0);
                atomicAdd(&red2[64 + cpair + 1], ss1);
            }
        }
    }

    if (uniform) {
        __syncthreads();
        if (tid < 64) {
            atomicAdd(&g_acc[OFF_S2 + g0 * D2 + tid], red2[tid]);
            atomicAdd(&g_acc[OFF_SS2 + g0 * D2 + tid], red2[64 + tid]);
        }
    }
}

// ---------------------------------------------------------------------------
// Gather-max: one warp per superpoint; lane handles channels (lane, lane+32).
__global__ void k_pool(float* __restrict__ out, int M) {
    int w = (blockIdx.x * blockDim.x + threadIdx.x) >> 5;
    int lane = threadIdx.x & 31;
    if (w >= M) return;
    int s = g_segoff[w], e = g_segoff[w + 1];
    float m0 = -3.402823466e38f, m1 = -3.402823466e38f;
    int row = (s < e) ? g_perm[s] : 0;
    for (int j = s; j < e; ++j) {
        int nrow = (j + 1 < e) ? g_perm[j + 1] : 0;
        int g = g_ni[row];
        size_t base = (size_t)row * D2;
        float v0 = g_h2[base + lane];
        float v1 = g_h2[base + 32 + lane];
        float a0 = v0 * g_scale2[g * D2 + lane] + g_shift2[g * D2 + lane];
        float a1 = v1 * g_scale2[g * D2 + 32 + lane] + g_shift2[g * D2 + 32 + lane];
        a0 = fmaxf(a0, SLOPE * a0);
        a1 = fmaxf(a1, SLOPE * a1);
        m0 = fmaxf(m0, a0);
        m1 = fmaxf(m1, a1);
        row = nrow;
    }
    if (s == e) { m0 = 0.f; m1 = 0.f; }
    out[(size_t)w * D2 + lane] = m0;
    out[(size_t)w * D2 + 32 + lane] = m1;
}

// ---------------------------------------------------------------------------
extern "C" void kernel_launch(void* const* d_in, const int* in_sizes, int n_in,
                              void* d_out, int out_size) {
    const float* x     = (const float*)d_in[0];
    const float* W1    = (const float*)d_in[1];
    const float* b1    = (const float*)d_in[2];
    const float* g1    = (const float*)d_in[3];
    const float* beta1 = (const float*)d_in[4];
    const float* W2    = (const float*)d_in[5];
    const float* b2    = (const float*)d_in[6];
    const float* g2    = (const float*)d_in[7];
    const float* beta2 = (const float*)d_in[8];
    const void*  nidx  = d_in[9];
    const void*  sidx  = d_in[10];
    float* out = (float*)d_out;

    int N = in_sizes[0] / D0;
    int M = out_size / D2;

    int zgrid = (max(M, ACC_TOT) + 255) / 256;
    int ngrid = (N + 255) / 256;
    int tgrid = (N + 127) / 128;

    cudaFuncSetAttribute(k_fused, cudaFuncAttributeMaxDynamicSharedMemorySize, FUSED_SMEM);

    k_detect<<<1, 32>>>(sidx, M);
    k_zero<<<zgrid, 256>>>(M);
    k_cvt<<<ngrid, 256>>>(nidx, sidx, N);
    k_hist<<<ngrid, 256>>>(N);
    k_scan<<<1, 1024>>>(M);
    k_fill<<<ngrid, 256>>>(N);
    k_stats1<<<tgrid, 256>>>(x, W1, b1, N);
    k_fin<<<(GG * D1 + 255) / 256, 256>>>(g1, beta1, 1);
    k_fused<<<tgrid, 256, FUSED_SMEM>>>(x, W1, b1, W2, b2, N);
    k_fin<<<(GG * D2 + 255) / 256, 256>>>(g2, beta2, 2);
    k_pool<<<(M + 7) / 8, 256>>>(out, M);
}

// round 3
// speedup vs baseline: 2.1499x; 1.5287x over previous
#include <cuda_runtime.h>
#include <cstdint>
#include <cstdio>

// ---------------------------------------------------------------------------
// NodeMLP: x[N,32] -> Linear(32,128) -> graphBN(G=16) -> LeakyReLU(0.01)
//          -> Linear(128,64) -> graphBN -> LeakyReLU -> segment_max into M
//
// R3: 512-thread tf32-MMA kernels, vectorized LDG.128/STS.128 tile moves,
//     conflict-free row-major smem layouts (stride % 32 == 4), fast scan,
//     merged cvt+hist, launch order puts GEMM kernels in the ncu sample slot.
// ---------------------------------------------------------------------------

constexpr int D0 = 32, D1 = 128, D2 = 64, GG = 16;
constexpr float EPS = 1e-5f;
constexpr float SLOPE = 0.01f;

constexpr size_t N_MAX = 1048576;
constexpr size_t M_MAX = 65536;

constexpr int OFF_S1 = 0, OFF_SS1 = 2048, OFF_S2 = 4096, OFF_SS2 = 5120, OFF_CNT = 6144;
constexpr int ACC_TOT = 6160;

__device__ float g_h2[N_MAX * (size_t)D2];   // raw (pre-norm) layer-2 output
__device__ float g_acc[ACC_TOT];
__device__ float g_scale1[GG * D1], g_shift1[GG * D1];
__device__ float g_scale2[GG * D2], g_shift2[GG * D2];
__device__ int   g_ni[N_MAX], g_si[N_MAX], g_perm[N_MAX];
__device__ int   g_segcnt[M_MAX], g_segoff[M_MAX + 1], g_cursor[M_MAX];
__device__ int   g_is64;

// ---------------------------------------------------------------------------
__device__ __forceinline__ uint32_t f2tf(float f) {
    uint32_t u;
    asm("cvt.rna.tf32.f32 %0, %1;" : "=r"(u) : "f"(f));
    return u;
}
__device__ __forceinline__ uint4 f4tf(float4 v) {
    return make_uint4(f2tf(v.x), f2tf(v.y), f2tf(v.z), f2tf(v.w));
}

// D += A(16x8,row) * B(8x8,col)   tf32 in, fp32 accum
__device__ __forceinline__ void mma_tf32(float* d, const uint32_t* a, const uint32_t* b) {
    asm volatile(
        "mma.sync.aligned.m16n8k8.row.col.f32.tf32.tf32.f32 "
        "{%0,%1,%2,%3}, {%4,%5,%6,%7}, {%8,%9}, {%0,%1,%2,%3};"
        : "+f"(d[0]), "+f"(d[1]), "+f"(d[2]), "+f"(d[3])
        : "r"(a[0]), "r"(a[1]), "r"(a[2]), "r"(a[3]), "r"(b[0]), "r"(b[1]));
}

// ---------------------------------------------------------------------------
__global__ void k_detect(const void* sidx, int M) {
    if (threadIdx.x == 0 && blockIdx.x == 0) {
        const long long* p = (const long long*)sidx;
        int ok64 = 1;
        for (int i = 0; i < 256; i++) {
            unsigned long long v = (unsigned long long)p[i];
            if (v >= (unsigned long long)M) { ok64 = 0; break; }
        }
        g_is64 = ok64;
    }
}

__global__ void k_zero(int M) {
    int i = blockIdx.x * blockDim.x + threadIdx.x;
    if (i < ACC_TOT) g_acc[i] = 0.f;
    if (i < M) { g_segcnt[i] = 0; g_cursor[i] = 0; }
}

// convert indices to int32 + histogram super_index in one pass
__global__ void k_cvthist(const void* nidx, const void* sidx, int N) {
    int i = blockIdx.x * blockDim.x + threadIdx.x;
    if (i >= N) return;
    int ni, si;
    if (g_is64) {
        ni = (int)((const long long*)nidx)[i];
        si = (int)((const long long*)sidx)[i];
    } else {
        ni = ((const int*)nidx)[i];
        si = ((const int*)sidx)[i];
    }
    g_ni[i] = ni;
    g_si[i] = si;
    atomicAdd(&g_segcnt[si], 1);
}

// fast two-level scan, single block of 1024 threads
__global__ void k_scan(int M) {
    __shared__ int wsum[32];
    int tid = threadIdx.x, lane = tid & 31, w = tid >> 5;
    int per = (M + 1023) >> 10;
    int s = tid * per;
    int e = min(s + per, M);
    int sum = 0;
    for (int i = s; i < e; i++) sum += g_segcnt[i];
    int v = sum;
#pragma unroll
    for (int off = 1; off < 32; off <<= 1) {
        int t = __shfl_up_sync(0xffffffffu, v, off);
        if (lane >= off) v += t;
    }
    if (lane == 31) wsum[w] = v;
    __syncthreads();
    if (w == 0) {
        int t = wsum[lane];
#pragma unroll
        for (int off = 1; off < 32; off <<= 1) {
            int u = __shfl_up_sync(0xffffffffu, t, off);
            if (lane >= off) t += u;
        }
        wsum[lane] = t;
    }
    __syncthreads();
    int run = (w ? wsum[w - 1] : 0) + (v - sum);
    for (int i = s; i < e; i++) { g_segoff[i] = run; run += g_segcnt[i]; }
    if (e == M) g_segoff[M] = run;
}

__global__ void k_fill(int N) {
    int i = blockIdx.x * blockDim.x + threadIdx.x;
    if (i >= N) return;
    int s = g_si[i];
    int pos = g_segoff[s] + atomicAdd(&g_cursor[s], 1);
    g_perm[pos] = i;
}

// ---------------------------------------------------------------------------
// GEMM1 warp fragment loop. Layouts: sA[128 rows][36 k-pad], sW[128 cols][36].
// 16 warps: rb0 = (wid>>1)*16 (8 row groups), cb = (wid&1)*64.
// Bank check: addr = r*36 + k0 -> (4*(lane>>2) + (lane&3)) mod 32: distinct.
__device__ __forceinline__ void gemm1_warp(
    const uint32_t (*sA)[36], const uint32_t (*sW)[36],
    int lane, int rb0, int cb, float acc[8][4])
{
#pragma unroll
    for (int ks = 0; ks < 4; ks++) {
        const int k0 = ks * 8 + (lane & 3);
        const int rb = rb0 + (lane >> 2);
        uint32_t a[4];
        a[0] = sA[rb][k0];     a[1] = sA[rb + 8][k0];
        a[2] = sA[rb][k0 + 4]; a[3] = sA[rb + 8][k0 + 4];
#pragma unroll
        for (int nf = 0; nf < 8; nf++) {
            const int cn = cb + nf * 8 + (lane >> 2);
            uint32_t b[2] = { sW[cn][k0], sW[cn][k0 + 4] };
            mma_tf32(acc[nf], a, b);
        }
    }
}

// ---------------------------------------------------------------------------
// Stats pass: GEMM1 -> per-graph sum/sumsq of h1 = xW1^T + b1.
__global__ __launch_bounds__(512) void k_stats1(
    const float* __restrict__ x, const float* __restrict__ W1,
    const float* __restrict__ b1, int N)
{
    __shared__ uint32_t sA[128][36];
    __shared__ uint32_t sW[128][36];
    __shared__ float red[2][128];
    __shared__ int sg[128];

    const int tid = threadIdx.x;
    const int r0 = blockIdx.x * 128;
    const int nrows = min(128, N - r0);

    for (int i = tid; i < 1024; i += 512) {
        int r = i >> 3, q = (i & 7) * 4;
        float4 v = (r < nrows) ? *(const float4*)&x[(size_t)(r0 + r) * D0 + q]
                               : make_float4(0.f, 0.f, 0.f, 0.f);
        *(uint4*)&sA[r][q] = f4tf(v);
    }
    for (int i = tid; i < 1024; i += 512) {
        int c = i >> 3, q = (i & 7) * 4;
        *(uint4*)&sW[c][q] = f4tf(*(const float4*)&W1[(size_t)c * D0 + q]);
    }
    if (tid < 128) {
        sg[tid] = (tid < nrows) ? g_ni[r0 + tid] : 0;
        red[0][tid] = 0.f; red[1][tid] = 0.f;
    }
    __syncthreads();

    const int lane = tid & 31, wid = tid >> 5;
    const int rb0 = (wid >> 1) * 16, cb = (wid & 1) * 64;

    float acc[8][4];
#pragma unroll
    for (int nf = 0; nf < 8; nf++)
#pragma unroll
        for (int q = 0; q < 4; q++) acc[nf][q] = 0.f;

    gemm1_warp(sA, sW, lane, rb0, cb, acc);

    const int g0 = sg[0];
    const bool uniform = (sg[nrows - 1] == g0);
    const int r1 = rb0 + (lane >> 2), r2 = r1 + 8;

    if (uniform) {
#pragma unroll
        for (int nf = 0; nf < 8; nf++) {
#pragma unroll
            for (int j = 0; j < 2; j++) {
                int c = cb + nf * 8 + 2 * (lane & 3) + j;
                float bias = __ldg(&b1[c]);
                float s = 0.f, ss = 0.f;
                if (r1 < nrows) { float h = acc[nf][j] + bias; s += h; ss += h * h; }
                if (r2 < nrows) { float h = acc[nf][j + 2] + bias; s += h; ss += h * h; }
#pragma unroll
                for (int off = 4; off < 32; off <<= 1) {
                    s  += __shfl_xor_sync(0xffffffffu, s, off);
                    ss += __shfl_xor_sync(0xffffffffu, ss, off);
                }
                if (lane < 4) { atomicAdd(&red[0][c], s); atomicAdd(&red[1][c], ss); }
            }
        }
        __syncthreads();
        if (tid < 128) {
            atomicAdd(&g_acc[OFF_S1 + g0 * D1 + tid], red[0][tid]);
            atomicAdd(&g_acc[OFF_SS1 + g0 * D1 + tid], red[1][tid]);
        }
        if (tid == 0) atomicAdd(&g_acc[OFF_CNT + g0], (float)nrows);
    } else {
#pragma unroll
        for (int nf = 0; nf < 8; nf++)
#pragma unroll
            for (int j = 0; j < 2; j++) {
                int c = cb + nf * 8 + 2 * (lane & 3) + j;
                float bias = __ldg(&b1[c]);
                if (r1 < nrows) {
                    float h = acc[nf][j] + bias;
                    int g = sg[r1];
                    atomicAdd(&g_acc[OFF_S1 + g * D1 + c], h);
                    atomicAdd(&g_acc[OFF_SS1 + g * D1 + c], h * h);
                }
                if (r2 < nrows) {
                    float h = acc[nf][j + 2] + bias;
                    int g = sg[r2];
                    atomicAdd(&g_acc[OFF_S1 + g * D1 + c], h);
                    atomicAdd(&g_acc[OFF_SS1 + g * D1 + c], h * h);
                }
            }
        if (tid < nrows) atomicAdd(&g_acc[OFF_CNT + sg[tid]], 1.0f);
    }
}

// per (g,ch): scale = gamma * rsqrt(var+eps), shift = beta - mean*scale
__global__ void k_fin(const float* __restrict__ gamma, const float* __restrict__ beta, int layer) {
    int D = (layer == 1) ? D1 : D2;
    const float* sum = (layer == 1) ? g_acc + OFF_S1 : g_acc + OFF_S2;
    const float* ss  = (layer == 1) ? g_acc + OFF_SS1 : g_acc + OFF_SS2;
    float* sc = (layer == 1) ? g_scale1 : g_scale2;
    float* sh = (layer == 1) ? g_shift1 : g_shift2;
    int i = blockIdx.x * blockDim.x + threadIdx.x;
    if (i >= GG * D) return;
    int g = i / D, ch = i % D;
    float c = fmaxf(g_acc[OFF_CNT + g], 1.f);
    float m = sum[i] / c;
    float var = fmaxf(ss[i] / c - m * m, 0.f);
    float s = gamma[ch] * rsqrtf(var + EPS);
    sc[i] = s;
    sh[i] = beta[ch] - m * s;
}

// ---------------------------------------------------------------------------
// Fused: GEMM1 (recompute) -> normalize+leaky into sH -> GEMM2 -> stats2
// -> store raw h2.
// Dynamic SMEM (bytes):
//   [0, 67584)         sH[128][132]  (tf32 normalized h1, row-major)
//   [67584, +36864)    phase1: sA[128][36] + sW1[128][36]; later sW2[64][132]
//   [104448, +512)     red2[128]
//   [104960, +512)     sg[128]
constexpr int SH_BYTES   = 128 * 132 * 4;          // 67584
constexpr int PH1_BYTES  = 2 * 128 * 36 * 4;       // 36864 (>= sW2: 64*132*4=33792)
constexpr int FUSED_SMEM = SH_BYTES + PH1_BYTES + 512 + 512;  // 105984

__global__ __launch_bounds__(512) void k_fused(
    const float* __restrict__ x, const float* __restrict__ W1,
    const float* __restrict__ b1, const float* __restrict__ W2,
    const float* __restrict__ b2, int N)
{
    extern __shared__ unsigned char dsm[];
    uint32_t (*sH)[132]  = (uint32_t(*)[132])dsm;
    uint32_t (*sA)[36]   = (uint32_t(*)[36])(dsm + SH_BYTES);
    uint32_t (*sW1)[36]  = (uint32_t(*)[36])(dsm + SH_BYTES + 128 * 36 * 4);
    uint32_t (*sW2)[132] = (uint32_t(*)[132])(dsm + SH_BYTES);
    float* red2 = (float*)(dsm + SH_BYTES + PH1_BYTES);   // [128]
    int*   sg   = (int*)(dsm + SH_BYTES + PH1_BYTES + 512);

    const int tid = threadIdx.x;
    const int r0 = blockIdx.x * 128;
    const int nrows = min(128, N - r0);

    for (int i = tid; i < 1024; i += 512) {
        int r = i >> 3, q = (i & 7) * 4;
        float4 v = (r < nrows) ? *(const float4*)&x[(size_t)(r0 + r) * D0 + q]
                               : make_float4(0.f, 0.f, 0.f, 0.f);
        *(uint4*)&sA[r][q] = f4tf(v);
    }
    for (int i = tid; i < 1024; i += 512) {
        int c = i >> 3, q = (i & 7) * 4;
        *(uint4*)&sW1[c][q] = f4tf(*(const float4*)&W1[(size_t)c * D0 + q]);
    }
    if (tid < 128) { sg[tid] = (tid < nrows) ? g_ni[r0 + tid] : 0; red2[tid] = 0.f; }
    __syncthreads();

    const int lane = tid & 31, wid = tid >> 5;
    const int rb0 = (wid >> 1) * 16, cb = (wid & 1) * 64;
    const int r1 = rb0 + (lane >> 2), r2 = r1 + 8;

    float acc[8][4];
#pragma unroll
    for (int nf = 0; nf < 8; nf++)
#pragma unroll
        for (int q = 0; q < 4; q++) acc[nf][q] = 0.f;

    gemm1_warp(sA, sW1, lane, rb0, cb, acc);
    __syncthreads();   // done reading sA/sW1; region becomes sW2

    const int g0 = sg[0];
    const bool uniform = (sg[nrows - 1] == g0);

    // normalize + leaky -> sH (bias folded into shift)
    if (uniform) {
        const float* scp = &g_scale1[g0 * D1];
        const float* shp = &g_shift1[g0 * D1];
#pragma unroll
        for (int nf = 0; nf < 8; nf++)
#pragma unroll
            for (int j = 0; j < 2; j++) {
                int c = cb + nf * 8 + 2 * (lane & 3) + j;
                float sc = __ldg(&scp[c]);
                float sh = __ldg(&b1[c]) * sc + __ldg(&shp[c]);
                float t1 = acc[nf][j] * sc + sh;
                float t2 = acc[nf][j + 2] * sc + sh;
                sH[r1][c] = f2tf(fmaxf(t1, SLOPE * t1));
                sH[r2][c] = f2tf(fmaxf(t2, SLOPE * t2));
            }
    } else {
        int gA = sg[r1], gB = sg[r2];
#pragma unroll
        for (int nf = 0; nf < 8; nf++)
#pragma unroll
            for (int j = 0; j < 2; j++) {
                int c = cb + nf * 8 + 2 * (lane & 3) + j;
                float bias = __ldg(&b1[c]);
                float sA1 = g_scale1[gA * D1 + c], sh1 = g_shift1[gA * D1 + c];
                float sA2 = g_scale1[gB * D1 + c], sh2 = g_shift1[gB * D1 + c];
                float t1 = (acc[nf][j] + bias) * sA1 + sh1;
                float t2 = (acc[nf][j + 2] + bias) * sA2 + sh2;
                sH[r1][c] = f2tf(fmaxf(t1, SLOPE * t1));
                sH[r2][c] = f2tf(fmaxf(t2, SLOPE * t2));
            }
    }

    // load W2 [64,128] row-major into sW2[n][k] (vectorized)
    for (int i = tid; i < 2048; i += 512) {
        int n = i >> 5, q = (i & 31) * 4;
        *(uint4*)&sW2[n][q] = f4tf(*(const float4*)&W2[(size_t)n * D1 + q]);
    }
    __syncthreads();

    // GEMM2: warp tile 16 rows x 32 cols, K=128
    const int cb2 = (wid & 1) * 32;
    float acc2[4][4];
#pragma unroll
    for (int nf = 0; nf < 4; nf++)
#pragma unroll
        for (int q = 0; q < 4; q++) acc2[nf][q] = 0.f;

#pragma unroll
    for (int ks = 0; ks < 16; ks++) {
        const int k0 = ks * 8 + (lane & 3);
        uint32_t a[4];
        a[0] = sH[r1][k0];     a[1] = sH[r2][k0];
        a[2] = sH[r1][k0 + 4]; a[3] = sH[r2][k0 + 4];
#pragma unroll
        for (int nf = 0; nf < 4; nf++) {
            const int cn = cb2 + nf * 8 + (lane >> 2);
            uint32_t b[2] = { sW2[cn][k0], sW2[cn][k0 + 4] };
            mma_tf32(acc2[nf], a, b);
        }
    }

    // epilogue: bias, stats2, store raw h2
#pragma unroll
    for (int nf = 0; nf < 4; nf++) {
        int cpair = cb2 + nf * 8 + 2 * (lane & 3);
        float bias0 = __ldg(&b2[cpair]);
        float bias1 = __ldg(&b2[cpair + 1]);
        float h0a = acc2[nf][0] + bias0, h1a = acc2[nf][1] + bias1;
        float h0b = acc2[nf][2] + bias0, h1b = acc2[nf][3] + bias1;
        if (r1 < nrows) *(float2*)&g_h2[(size_t)(r0 + r1) * D2 + cpair] = make_float2(h0a, h1a);
        if (r2 < nrows) *(float2*)&g_h2[(size_t)(r0 + r2) * D2 + cpair] = make_float2(h0b, h1b);
        if (uniform) {
            float s0 = 0.f, ss0 = 0.f, s1 = 0.f, ss1 = 0.f;
            if (r1 < nrows) { s0 += h0a; ss0 += h0a * h0a; s1 += h1a; ss1 += h1a * h1a; }
            if (r2 < nrows) { s0 += h0b; ss0 += h0b * h0b; s1 += h1b; ss1 += h1b * h1b; }
#pragma unroll
            for (int off = 4; off < 32; off <<= 1) {
                s0  += __shfl_xor_sync(0xffffffffu, s0, off);
                ss0 += __shfl_xor_sync(0xffffffffu, ss0, off);
                s1  += __shfl_xor_sync(0xffffffffu, s1, off);
                ss1 += __shfl_xor_sync(0xffffffffu, ss1, off);
            }
            if (lane < 4) {
                atomicAdd(&red2[cpair], s0);
                atomicAdd(&red2[cpair + 1], s1);
                atomicAdd(&red2[64 + cpair], ss0);
                atomicAdd(&red2[64 + cpair + 1], ss1);
            }
        } else {
            if (r1 < nrows) {
                int g = sg[r1];
                atomicAdd(&g_acc[OFF_S2 + g * D2 + cpair], h0a);
                atomicAdd(&g_acc[OFF_SS2 + g * D2 + cpair], h0a * h0a);
                atomicAdd(&g_acc[OFF_S2 + g * D2 + cpair + 1], h1a);
                atomicAdd(&g_acc[OFF_SS2 + g * D2 + cpair + 1], h1a * h1a);
            }
            if (r2 < nrows) {
                int g = sg[r2];
                atomicAdd(&g_acc[OFF_S2 + g * D2 + cpair], h0b);
                atomicAdd(&g_acc[OFF_SS2 + g * D2 + cpair], h0b * h0b);
                atomicAdd(&g_acc[OFF_S2 + g * D2 + cpair + 1], h1b);
                atomicAdd(&g_acc[OFF_SS2 + g * D2 + cpair + 1], h1b * h1b);
            }
        }
    }

    if (uniform) {
        __syncthreads();
        if (tid < 64) {
            atomicAdd(&g_acc[OFF_S2 + g0 * D2 + tid], red2[tid]);
            atomicAdd(&g_acc[OFF_SS2 + g0 * D2 + tid], red2[64 + tid]);
        }
    }
}

// ---------------------------------------------------------------------------
// Gather-max: one warp per superpoint; lane handles channels (lane, lane+32).
__global__ void k_pool(float* __restrict__ out, int M) {
    int w = (blockIdx.x * blockDim.x + threadIdx.x) >> 5;
    int lane = threadIdx.x & 31;
    if (w >= M) return;
    int s = g_segoff[w], e = g_segoff[w + 1];
    float m0 = -3.402823466e38f, m1 = -3.402823466e38f;
    int row = (s < e) ? g_perm[s] : 0;
    for (int j = s; j < e; ++j) {
        int nrow = (j + 1 < e) ? g_perm[j + 1] : 0;
        int g = g_ni[row];
        size_t base = (size_t)row * D2;
        float v0 = g_h2[base + lane];
        float v1 = g_h2[base + 32 + lane];
        float a0 = v0 * g_scale2[g * D2 + lane] + g_shift2[g * D2 + lane];
        float a1 = v1 * g_scale2[g * D2 + 32 + lane] + g_shift2[g * D2 + 32 + lane];
        a0 = fmaxf(a0, SLOPE * a0);
        a1 = fmaxf(a1, SLOPE * a1);
        m0 = fmaxf(m0, a0);
        m1 = fmaxf(m1, a1);
        row = nrow;
    }
    if (s == e) { m0 = 0.f; m1 = 0.f; }
    out[(size_t)w * D2 + lane] = m0;
    out[(size_t)w * D2 + 32 + lane] = m1;
}

// ---------------------------------------------------------------------------
extern "C" void kernel_launch(void* const* d_in, const int* in_sizes, int n_in,
                              void* d_out, int out_size) {
    const float* x     = (const float*)d_in[0];
    const float* W1    = (const float*)d_in[1];
    const float* b1    = (const float*)d_in[2];
    const float* g1    = (const float*)d_in[3];
    const float* beta1 = (const float*)d_in[4];
    const float* W2    = (const float*)d_in[5];
    const float* b2    = (const float*)d_in[6];
    const float* g2    = (const float*)d_in[7];
    const float* beta2 = (const float*)d_in[8];
    const void*  nidx  = d_in[9];
    const void*  sidx  = d_in[10];
    float* out = (float*)d_out;

    int N = in_sizes[0] / D0;
    int M = out_size / D2;

    int zgrid = (max(M, ACC_TOT) + 255) / 256;
    int ngrid = (N + 255) / 256;
    int tgrid = (N + 127) / 128;

    cudaFuncSetAttribute(k_fused, cudaFuncAttributeMaxDynamicSharedMemorySize, FUSED_SMEM);

    // heavy kernels early so the ncu sample (-s 5 -c 1) lands on them
    k_detect<<<1, 32>>>(sidx, M);
    k_zero<<<zgrid, 256>>>(M);
    k_cvthist<<<ngrid, 256>>>(nidx, sidx, N);
    k_stats1<<<tgrid, 512>>>(x, W1, b1, N);
    k_fin<<<(GG * D1 + 255) / 256, 256>>>(g1, beta1, 1);
    k_fused<<<tgrid, 512, FUSED_SMEM>>>(x, W1, b1, W2, b2, N);
    k_fin<<<(GG * D2 + 255) / 256, 256>>>(g2, beta2, 2);
    k_scan<<<1, 1024>>>(M);
    k_fill<<<ngrid, 256>>>(N);
    k_pool<<<(M + 7) / 8, 256>>>(out, M);
}

// round 4
// speedup vs baseline: 2.1520x; 1.0010x over previous
#include <cuda_runtime.h>
#include <cstdint>
#include <cstdio>

// ---------------------------------------------------------------------------
// NodeMLP: x[N,32] -> Linear(32,128) -> graphBN(G=16) -> LeakyReLU(0.01)
//          -> Linear(128,64) -> graphBN -> LeakyReLU -> segment_max into M
//
// R3: 512-thread tf32-MMA kernels, vectorized LDG.128/STS.128 tile moves,
//     conflict-free row-major smem layouts (stride % 32 == 4), fast scan,
//     merged cvt+hist, launch order puts GEMM kernels in the ncu sample slot.
// ---------------------------------------------------------------------------

constexpr int D0 = 32, D1 = 128, D2 = 64, GG = 16;
constexpr float EPS = 1e-5f;
constexpr float SLOPE = 0.01f;

constexpr size_t N_MAX = 1048576;
constexpr size_t M_MAX = 65536;

constexpr int OFF_S1 = 0, OFF_SS1 = 2048, OFF_S2 = 4096, OFF_SS2 = 5120, OFF_CNT = 6144;
constexpr int ACC_TOT = 6160;

__device__ float g_h2[N_MAX * (size_t)D2];   // raw (pre-norm) layer-2 output
__device__ float g_acc[ACC_TOT];
__device__ float g_scale1[GG * D1], g_shift1[GG * D1];
__device__ float g_scale2[GG * D2], g_shift2[GG * D2];
__device__ int   g_ni[N_MAX], g_si[N_MAX], g_perm[N_MAX];
__device__ int   g_segcnt[M_MAX], g_segoff[M_MAX + 1], g_cursor[M_MAX];
__device__ int   g_is64;

// ---------------------------------------------------------------------------
__device__ __forceinline__ uint32_t f2tf(float f) {
    uint32_t u;
    asm("cvt.rna.tf32.f32 %0, %1;" : "=r"(u) : "f"(f));
    return u;
}
__device__ __forceinline__ uint4 f4tf(float4 v) {
    return make_uint4(f2tf(v.x), f2tf(v.y), f2tf(v.z), f2tf(v.w));
}

// D += A(16x8,row) * B(8x8,col)   tf32 in, fp32 accum
__device__ __forceinline__ void mma_tf32(float* d, const uint32_t* a, const uint32_t* b) {
    asm volatile(
        "mma.sync.aligned.m16n8k8.row.col.f32.tf32.tf32.f32 "
        "{%0,%1,%2,%3}, {%4,%5,%6,%7}, {%8,%9}, {%0,%1,%2,%3};"
        : "+f"(d[0]), "+f"(d[1]), "+f"(d[2]), "+f"(d[3])
        : "r"(a[0]), "r"(a[1]), "r"(a[2]), "r"(a[3]), "r"(b[0]), "r"(b[1]));
}

// ---------------------------------------------------------------------------
__global__ void k_detect(const void* sidx, int M) {
    if (threadIdx.x == 0 && blockIdx.x == 0) {
        const long long* p = (const long long*)sidx;
        int ok64 = 1;
        for (int i = 0; i < 256; i++) {
            unsigned long long v = (unsigned long long)p[i];
            if (v >= (unsigned long long)M) { ok64 = 0; break; }
        }
        g_is64 = ok64;
    }
}

__global__ void k_zero(int M) {
    int i = blockIdx.x * blockDim.x + threadIdx.x;
    if (i < ACC_TOT) g_acc[i] = 0.f;
    if (i < M) { g_segcnt[i] = 0; g_cursor[i] = 0; }
}

// convert indices to int32 + histogram super_index in one pass
__global__ void k_cvthist(const void* nidx, const void* sidx, int N) {
    int i = blockIdx.x * blockDim.x + threadIdx.x;
    if (i >= N) return;
    int ni, si;
    if (g_is64) {
        ni = (int)((const long long*)nidx)[i];
        si = (int)((const long long*)sidx)[i];
    } else {
        ni = ((const int*)nidx)[i];
        si = ((const int*)sidx)[i];
    }
    g_ni[i] = ni;
    g_si[i] = si;
    atomicAdd(&g_segcnt[si], 1);
}

// fast two-level scan, single block of 1024 threads
__global__ void k_scan(int M) {
    __shared__ int wsum[32];
    int tid = threadIdx.x, lane = tid & 31, w = tid >> 5;
    int per = (M + 1023) >> 10;
    int s = tid * per;
    int e = min(s + per, M);
    int sum = 0;
    for (int i = s; i < e; i++) sum += g_segcnt[i];
    int v = sum;
#pragma unroll
    for (int off = 1; off < 32; off <<= 1) {
        int t = __shfl_up_sync(0xffffffffu, v, off);
        if (lane >= off) v += t;
    }
    if (lane == 31) wsum[w] = v;
    __syncthreads();
    if (w == 0) {
        int t = wsum[lane];
#pragma unroll
        for (int off = 1; off < 32; off <<= 1) {
            int u = __shfl_up_sync(0xffffffffu, t, off);
            if (lane >= off) t += u;
        }
        wsum[lane] = t;
    }
    __syncthreads();
    int run = (w ? wsum[w - 1] : 0) + (v - sum);
    for (int i = s; i < e; i++) { g_segoff[i] = run; run += g_segcnt[i]; }
    if (e == M) g_segoff[M] = run;
}

__global__ void k_fill(int N) {
    int i = blockIdx.x * blockDim.x + threadIdx.x;
    if (i >= N) return;
    int s = g_si[i];
    int pos = g_segoff[s] + atomicAdd(&g_cursor[s], 1);
    g_perm[pos] = i;
}

// ---------------------------------------------------------------------------
// GEMM1 warp fragment loop. Layouts: sA[128 rows][36 k-pad], sW[128 cols][36].
// 16 warps: rb0 = (wid>>1)*16 (8 row groups), cb = (wid&1)*64.
// Bank check: addr = r*36 + k0 -> (4*(lane>>2) + (lane&3)) mod 32: distinct.
__device__ __forceinline__ void gemm1_warp(
    const uint32_t (*sA)[36], const uint32_t (*sW)[36],
    int lane, int rb0, int cb, float acc[8][4])
{
#pragma unroll
    for (int ks = 0; ks < 4; ks++) {
        const int k0 = ks * 8 + (lane & 3);
        const int rb = rb0 + (lane >> 2);
        uint32_t a[4];
        a[0] = sA[rb][k0];     a[1] = sA[rb + 8][k0];
        a[2] = sA[rb][k0 + 4]; a[3] = sA[rb + 8][k0 + 4];
#pragma unroll
        for (int nf = 0; nf < 8; nf++) {
            const int cn = cb + nf * 8 + (lane >> 2);
            uint32_t b[2] = { sW[cn][k0], sW[cn][k0 + 4] };
            mma_tf32(acc[nf], a, b);
        }
    }
}

// ---------------------------------------------------------------------------
// Stats pass: GEMM1 -> per-graph sum/sumsq of h1 = xW1^T + b1.
__global__ __launch_bounds__(512) void k_stats1(
    const float* __restrict__ x, const float* __restrict__ W1,
    const float* __restrict__ b1, int N)
{
    __shared__ uint32_t sA[128][36];
    __shared__ uint32_t sW[128][36];
    __shared__ float red[2][128];
    __shared__ int sg[128];

    const int tid = threadIdx.x;
    const int r0 = blockIdx.x * 128;
    const int nrows = min(128, N - r0);

    for (int i = tid; i < 1024; i += 512) {
        int r = i >> 3, q = (i & 7) * 4;
        float4 v = (r < nrows) ? *(const float4*)&x[(size_t)(r0 + r) * D0 + q]
                               : make_float4(0.f, 0.f, 0.f, 0.f);
        *(uint4*)&sA[r][q] = f4tf(v);
    }
    for (int i = tid; i < 1024; i += 512) {
        int c = i >> 3, q = (i & 7) * 4;
        *(uint4*)&sW[c][q] = f4tf(*(const float4*)&W1[(size_t)c * D0 + q]);
    }
    if (tid < 128) {
        sg[tid] = (tid < nrows) ? g_ni[r0 + tid] : 0;
        red[0][tid] = 0.f; red[1][tid] = 0.f;
    }
    __syncthreads();

    const int lane = tid & 31, wid = tid >> 5;
    const int rb0 = (wid >> 1) * 16, cb = (wid & 1) * 64;

    float acc[8][4];
#pragma unroll
    for (int nf = 0; nf < 8; nf++)
#pragma unroll
        for (int q = 0; q < 4; q++) acc[nf][q] = 0.f;

    gemm1_warp(sA, sW, lane, rb0, cb, acc);

    const int g0 = sg[0];
    const bool uniform = (sg[nrows - 1] == g0);
    const int r1 = rb0 + (lane >> 2), r2 = r1 + 8;

    if (uniform) {
#pragma unroll
        for (int nf = 0; nf < 8; nf++) {
#pragma unroll
            for (int j = 0; j < 2; j++) {
                int c = cb + nf * 8 + 2 * (lane & 3) + j;
                float bias = __ldg(&b1[c]);
                float s = 0.f, ss = 0.f;
                if (r1 < nrows) { float h = acc[nf][j] + bias; s += h; ss += h * h; }
                if (r2 < nrows) { float h = acc[nf][j + 2] + bias; s += h; ss += h * h; }
#pragma unroll
                for (int off = 4; off < 32; off <<= 1) {
                    s  += __shfl_xor_sync(0xffffffffu, s, off);
                    ss += __shfl_xor_sync(0xffffffffu, ss, off);
                }
                if (lane < 4) { atomicAdd(&red[0][c], s); atomicAdd(&red[1][c], ss); }
            }
        }
        __syncthreads();
        if (tid < 128) {
            atomicAdd(&g_acc[OFF_S1 + g0 * D1 + tid], red[0][tid]);
            atomicAdd(&g_acc[OFF_SS1 + g0 * D1 + tid], red[1][tid]);
        }
        if (tid == 0) atomicAdd(&g_acc[OFF_CNT + g0], (float)nrows);
    } else {
#pragma unroll
        for (int nf = 0; nf < 8; nf++)
#pragma unroll
            for (int j = 0; j < 2; j++) {
                int c = cb + nf * 8 + 2 * (lane & 3) + j;
                float bias = __ldg(&b1[c]);
                if (r1 < nrows) {
                    float h = acc[nf][j] + bias;
                    int g = sg[r1];
                    atomicAdd(&g_acc[OFF_S1 + g * D1 + c], h);
                    atomicAdd(&g_acc[OFF_SS1 + g * D1 + c], h * h);
                }
                if (r2 < nrows) {
                    float h = acc[nf][j + 2] + bias;
                    int g = sg[r2];
                    atomicAdd(&g_acc[OFF_S1 + g * D1 + c], h);
                    atomicAdd(&g_acc[OFF_SS1 + g * D1 + c], h * h);
                }
            }
        if (tid < nrows) atomicAdd(&g_acc[OFF_CNT + sg[tid]], 1.0f);
    }
}

// per (g,ch): scale = gamma * rsqrt(var+eps), shift = beta - mean*scale
__global__ void k_fin(const float* __restrict__ gamma, const float* __restrict__ beta, int layer) {
    int D = (layer == 1) ? D1 : D2;
    const float* sum = (layer == 1) ? g_acc + OFF_S1 : g_acc + OFF_S2;
    const float* ss  = (layer == 1) ? g_acc + OFF_SS1 : g_acc + OFF_SS2;
    float* sc = (layer == 1) ? g_scale1 : g_scale2;
    float* sh = (layer == 1) ? g_shift1 : g_shift2;
    int i = blockIdx.x * blockDim.x + threadIdx.x;
    if (i >= GG * D) return;
    int g = i / D, ch = i % D;
    float c = fmaxf(g_acc[OFF_CNT + g], 1.f);
    float m = sum[i] / c;
    float var = fmaxf(ss[i] / c - m * m, 0.f);
    float s = gamma[ch] * rsqrtf(var + EPS);
    sc[i] = s;
    sh[i] = beta[ch] - m * s;
}

// ---------------------------------------------------------------------------
// Fused: GEMM1 (recompute) -> normalize+leaky into sH -> GEMM2 -> stats2
// -> store raw h2.
// Dynamic SMEM (bytes):
//   [0, 67584)         sH[128][132]  (tf32 normalized h1, row-major)
//   [67584, +36864)    phase1: sA[128][36] + sW1[128][36]; later sW2[64][132]
//   [104448, +512)     red2[128]
//   [104960, +512)     sg[128]
constexpr int SH_BYTES   = 128 * 132 * 4;          // 67584
constexpr int PH1_BYTES  = 2 * 128 * 36 * 4;       // 36864 (>= sW2: 64*132*4=33792)
constexpr int FUSED_SMEM = SH_BYTES + PH1_BYTES + 512 + 512;  // 105984

__global__ __launch_bounds__(512) void k_fused(
    const float* __restrict__ x, const float* __restrict__ W1,
    const float* __restrict__ b1, const float* __restrict__ W2,
    const float* __restrict__ b2, int N)
{
    extern __shared__ unsigned char dsm[];
    uint32_t (*sH)[132]  = (uint32_t(*)[132])dsm;
    uint32_t (*sA)[36]   = (uint32_t(*)[36])(dsm + SH_BYTES);
    uint32_t (*sW1)[36]  = (uint32_t(*)[36])(dsm + SH_BYTES + 128 * 36 * 4);
    uint32_t (*sW2)[132] = (uint32_t(*)[132])(dsm + SH_BYTES);
    float* red2 = (float*)(dsm + SH_BYTES + PH1_BYTES);   // [128]
    int*   sg   = (int*)(dsm + SH_BYTES + PH1_BYTES + 512);

    const int tid = threadIdx.x;
    const int r0 = blockIdx.x * 128;
    const int nrows = min(128, N - r0);

    for (int i = tid; i < 1024; i += 512) {
        int r = i >> 3, q = (i & 7) * 4;
        float4 v = (r < nrows) ? *(const float4*)&x[(size_t)(r0 + r) * D0 + q]
                               : make_float4(0.f, 0.f, 0.f, 0.f);
        *(uint4*)&sA[r][q] = f4tf(v);
    }
    for (int i = tid; i < 1024; i += 512) {
        int c = i >> 3, q = (i & 7) * 4;
        *(uint4*)&sW1[c][q] = f4tf(*(const float4*)&W1[(size_t)c * D0 + q]);
    }
    if (tid < 128) { sg[tid] = (tid < nrows) ? g_ni[r0 + tid] : 0; red2[tid] = 0.f; }
    __syncthreads();

    const int lane = tid & 31, wid = tid >> 5;
    const int rb0 = (wid >> 1) * 16, cb = (wid & 1) * 64;
    const int r1 = rb0 + (lane >> 2), r2 = r1 + 8;

    float acc[8][4];
#pragma unroll
    for (int nf = 0; nf < 8; nf++)
#pragma unroll
        for (int q = 0; q < 4; q++) acc[nf][q] = 0.f;

    gemm1_warp(sA, sW1, lane, rb0, cb, acc);
    __syncthreads();   // done reading sA/sW1; region becomes sW2

    const int g0 = sg[0];
    const bool uniform = (sg[nrows - 1] == g0);

    // normalize + leaky -> sH (bias folded into shift)
    if (uniform) {
        const float* scp = &g_scale1[g0 * D1];
        const float* shp = &g_shift1[g0 * D1];
#pragma unroll
        for (int nf = 0; nf < 8; nf++)
#pragma unroll
            for (int j = 0; j < 2; j++) {
                int c = cb + nf * 8 + 2 * (lane & 3) + j;
                float sc = __ldg(&scp[c]);
                float sh = __ldg(&b1[c]) * sc + __ldg(&shp[c]);
                float t1 = acc[nf][j] * sc + sh;
                float t2 = acc[nf][j + 2] * sc + sh;
                sH[r1][c] = f2tf(fmaxf(t1, SLOPE * t1));
                sH[r2][c] = f2tf(fmaxf(t2, SLOPE * t2));
            }
    } else {
        int gA = sg[r1], gB = sg[r2];
#pragma unroll
        for (int nf = 0; nf < 8; nf++)
#pragma unroll
            for (int j = 0; j < 2; j++) {
                int c = cb + nf * 8 + 2 * (lane & 3) + j;
                float bias = __ldg(&b1[c]);
                float sA1 = g_scale1[gA * D1 + c], sh1 = g_shift1[gA * D1 + c];
                float sA2 = g_scale1[gB * D1 + c], sh2 = g_shift1[gB * D1 + c];
                float t1 = (acc[nf][j] + bias) * sA1 + sh1;
                float t2 = (acc[nf][j + 2] + bias) * sA2 + sh2;
                sH[r1][c] = f2tf(fmaxf(t1, SLOPE * t1));
                sH[r2][c] = f2tf(fmaxf(t2, SLOPE * t2));
            }
    }

    // load W2 [64,128] row-major into sW2[n][k] (vectorized)
    for (int i = tid; i < 2048; i += 512) {
        int n = i >> 5, q = (i & 31) * 4;
        *(uint4*)&sW2[n][q] = f4tf(*(const float4*)&W2[(size_t)n * D1 + q]);
    }
    __syncthreads();

    // GEMM2: warp tile 16 rows x 32 cols, K=128
    const int cb2 = (wid & 1) * 32;
    float acc2[4][4];
#pragma unroll
    for (int nf = 0; nf < 4; nf++)
#pragma unroll
        for (int q = 0; q < 4; q++) acc2[nf][q] = 0.f;

#pragma unroll
    for (int ks = 0; ks < 16; ks++) {
        const int k0 = ks * 8 + (lane & 3);
        uint32_t a[4];
        a[0] = sH[r1][k0];     a[1] = sH[r2][k0];
        a[2] = sH[r1][k0 + 4]; a[3] = sH[r2][k0 + 4];
#pragma unroll
        for (int nf = 0; nf < 4; nf++) {
            const int cn = cb2 + nf * 8 + (lane >> 2);
            uint32_t b[2] = { sW2[cn][k0], sW2[cn][k0 + 4] };
            mma_tf32(acc2[nf], a, b);
        }
    }

    // epilogue: bias, stats2, store raw h2
#pragma unroll
    for (int nf = 0; nf < 4; nf++) {
        int cpair = cb2 + nf * 8 + 2 * (lane & 3);
        float bias0 = __ldg(&b2[cpair]);
        float bias1 = __ldg(&b2[cpair + 1]);
        float h0a = acc2[nf][0] + bias0, h1a = acc2[nf][1] + bias1;
        float h0b = acc2[nf][2] + bias0, h1b = acc2[nf][3] + bias1;
        if (r1 < nrows) *(float2*)&g_h2[(size_t)(r0 + r1) * D2 + cpair] = make_float2(h0a, h1a);
        if (r2 < nrows) *(float2*)&g_h2[(size_t)(r0 + r2) * D2 + cpair] = make_float2(h0b, h1b);
        if (uniform) {
            float s0 = 0.f, ss0 = 0.f, s1 = 0.f, ss1 = 0.f;
            if (r1 < nrows) { s0 += h0a; ss0 += h0a * h0a; s1 += h1a; ss1 += h1a * h1a; }
            if (r2 < nrows) { s0 += h0b; ss0 += h0b * h0b; s1 += h1b; ss1 += h1b * h1b; }
#pragma unroll
            for (int off = 4; off < 32; off <<= 1) {
                s0  += __shfl_xor_sync(0xffffffffu, s0, off);
                ss0 += __shfl_xor_sync(0xffffffffu, ss0, off);
                s1  += __shfl_xor_sync(0xffffffffu, s1, off);
                ss1 += __shfl_xor_sync(0xffffffffu, ss1, off);
            }
            if (lane < 4) {
                atomicAdd(&red2[cpair], s0);
                atomicAdd(&red2[cpair + 1], s1);
                atomicAdd(&red2[64 + cpair], ss0);
                atomicAdd(&red2[64 + cpair + 1], ss1);
            }
        } else {
            if (r1 < nrows) {
                int g = sg[r1];
                atomicAdd(&g_acc[OFF_S2 + g * D2 + cpair], h0a);
                atomicAdd(&g_acc[OFF_SS2 + g * D2 + cpair], h0a * h0a);
                atomicAdd(&g_acc[OFF_S2 + g * D2 + cpair + 1], h1a);
                atomicAdd(&g_acc[OFF_SS2 + g * D2 + cpair + 1], h1a * h1a);
            }
            if (r2 < nrows) {
                int g = sg[r2];
                atomicAdd(&g_acc[OFF_S2 + g * D2 + cpair], h0b);
                atomicAdd(&g_acc[OFF_SS2 + g * D2 + cpair], h0b * h0b);
                atomicAdd(&g_acc[OFF_S2 + g * D2 + cpair + 1], h1b);
                atomicAdd(&g_acc[OFF_SS2 + g * D2 + cpair + 1], h1b * h1b);
            }
        }
    }

    if (uniform) {
        __syncthreads();
        if (tid < 64) {
            atomicAdd(&g_acc[OFF_S2 + g0 * D2 + tid], red2[tid]);
            atomicAdd(&g_acc[OFF_SS2 + g0 * D2 + tid], red2[64 + tid]);
        }
    }
}

// ---------------------------------------------------------------------------
// Gather-max: one warp per superpoint; lane handles channels (lane, lane+32).
__global__ void k_pool(float* __restrict__ out, int M) {
    int w = (blockIdx.x * blockDim.x + threadIdx.x) >> 5;
    int lane = threadIdx.x & 31;
    if (w >= M) return;
    int s = g_segoff[w], e = g_segoff[w + 1];
    float m0 = -3.402823466e38f, m1 = -3.402823466e38f;
    int row = (s < e) ? g_perm[s] : 0;
    for (int j = s; j < e; ++j) {
        int nrow = (j + 1 < e) ? g_perm[j + 1] : 0;
        int g = g_ni[row];
        size_t base = (size_t)row * D2;
        float v0 = g_h2[base + lane];
        float v1 = g_h2[base + 32 + lane];
        float a0 = v0 * g_scale2[g * D2 + lane] + g_shift2[g * D2 + lane];
        float a1 = v1 * g_scale2[g * D2 + 32 + lane] + g_shift2[g * D2 + 32 + lane];
        a0 = fmaxf(a0, SLOPE * a0);
        a1 = fmaxf(a1, SLOPE * a1);
        m0 = fmaxf(m0, a0);
        m1 = fmaxf(m1, a1);
        row = nrow;
    }
    if (s == e) { m0 = 0.f; m1 = 0.f; }
    out[(size_t)w * D2 + lane] = m0;
    out[(size_t)w * D2 + 32 + lane] = m1;
}

// ---------------------------------------------------------------------------
extern "C" void kernel_launch(void* const* d_in, const int* in_sizes, int n_in,
                              void* d_out, int out_size) {
    const float* x     = (const float*)d_in[0];
    const float* W1    = (const float*)d_in[1];
    const float* b1    = (const float*)d_in[2];
    const float* g1    = (const float*)d_in[3];
    const float* beta1 = (const float*)d_in[4];
    const float* W2    = (const float*)d_in[5];
    const float* b2    = (const float*)d_in[6];
    const float* g2    = (const float*)d_in[7];
    const float* beta2 = (const float*)d_in[8];
    const void*  nidx  = d_in[9];
    const void*  sidx  = d_in[10];
    float* out = (float*)d_out;

    int N = in_sizes[0] / D0;
    int M = out_size / D2;

    int zgrid = (max(M, ACC_TOT) + 255) / 256;
    int ngrid = (N + 255) / 256;
    int tgrid = (N + 127) / 128;

    cudaFuncSetAttribute(k_fused, cudaFuncAttributeMaxDynamicSharedMemorySize, FUSED_SMEM);

    // heavy kernels early so the ncu sample (-s 5 -c 1) lands on them
    k_detect<<<1, 32>>>(sidx, M);
    k_zero<<<zgrid, 256>>>(M);
    k_cvthist<<<ngrid, 256>>>(nidx, sidx, N);
    k_stats1<<<tgrid, 512>>>(x, W1, b1, N);
    k_fin<<<(GG * D1 + 255) / 256, 256>>>(g1, beta1, 1);
    k_fused<<<tgrid, 512, FUSED_SMEM>>>(x, W1, b1, W2, b2, N);
    k_fin<<<(GG * D2 + 255) / 256, 256>>>(g2, beta2, 2);
    k_scan<<<1, 1024>>>(M);
    k_fill<<<ngrid, 256>>>(N);
    k_pool<<<(M + 7) / 8, 256>>>(out, M);
}

// round 6
// speedup vs baseline: 2.1758x; 1.0111x over previous
#include <cuda_runtime.h>
#include <cstdint>

// ---------------------------------------------------------------------------
// NodeMLP: x[N,32] -> Linear(32,128) -> graphBN(G=16) -> LeakyReLU(0.01)
//          -> Linear(128,64) -> graphBN -> LeakyReLU -> segment_max into M
//
// R5: layer-1 stats computed ANALYTICALLY from per-graph moments of x
//     (S_g = sum x x^T via tf32 mma, m_g = sum x): kills k_stats1.
//     k_fused mainloops use permuted smem layout -> all fragment loads LDS.64.
// ---------------------------------------------------------------------------

constexpr int D0 = 32, D1 = 128, D2 = 64, GG = 16;
constexpr float EPS = 1e-5f;
constexpr float SLOPE = 0.01f;

constexpr size_t N_MAX = 1048576;
constexpr size_t M_MAX = 65536;

// layer-2 stats accumulators: [0,1024) sum, [1024,2048) sumsq  ([g][64])
constexpr int OFF_S2 = 0, OFF_SS2 = 1024, ACC_TOT = 2048;

__device__ float g_h2[N_MAX * (size_t)D2];   // raw (pre-norm) layer-2 output
__device__ float g_acc[ACC_TOT];
__device__ float g_S[GG * 1024];             // per-graph x^T x (32x32)
__device__ float g_m[GG * 32];               // per-graph sum x
__device__ float g_scale1[GG * D1], g_shift1[GG * D1];
__device__ float g_scale2[GG * D2], g_shift2[GG * D2];
__device__ int   g_ni[N_MAX], g_si[N_MAX], g_perm[N_MAX];
__device__ int   g_segcnt[M_MAX], g_segoff[M_MAX + 1], g_cursor[M_MAX];
__device__ int   g_is64;

// ---------------------------------------------------------------------------
__device__ __forceinline__ uint32_t f2tf(float f) {
    uint32_t u;
    asm("cvt.rna.tf32.f32 %0, %1;" : "=r"(u) : "f"(f));
    return u;
}

// D += A(16x8,row) * B(8x8,col)   tf32 in, fp32 accum
__device__ __forceinline__ void mma_tf32(float* d, const uint32_t* a, const uint32_t* b) {
    asm volatile(
        "mma.sync.aligned.m16n8k8.row.col.f32.tf32.tf32.f32 "
        "{%0,%1,%2,%3}, {%4,%5,%6,%7}, {%8,%9}, {%0,%1,%2,%3};"
        : "+f"(d[0]), "+f"(d[1]), "+f"(d[2]), "+f"(d[3])
        : "r"(a[0]), "r"(a[1]), "r"(a[2]), "r"(a[3]), "r"(b[0]), "r"(b[1]));
}

// permuted position of k within its 8-group: (k,k+4) become adjacent
__device__ __forceinline__ int kperm(int k) {
    return (k & ~7) | ((k & 3) << 1) | ((k >> 2) & 1);
}

// first index i in sorted g_ni[0..n) with g_ni[i] >= v
__device__ __forceinline__ int lbound(int n, int v) {
    int lo = 0, hi = n;
    while (lo < hi) {
        int mid = (lo + hi) >> 1;
        if (g_ni[mid] < v) lo = mid + 1; else hi = mid;
    }
    return lo;
}

// ---------------------------------------------------------------------------
__global__ void k_detect(const void* sidx, int M) {
    if (threadIdx.x == 0 && blockIdx.x == 0) {
        const long long* p = (const long long*)sidx;
        int ok64 = 1;
        for (int i = 0; i < 256; i++) {
            unsigned long long v = (unsigned long long)p[i];
            if (v >= (unsigned long long)M) { ok64 = 0; break; }
        }
        g_is64 = ok64;
    }
}

__global__ void k_zero(int M) {
    int i = blockIdx.x * blockDim.x + threadIdx.x;
    if (i < ACC_TOT) g_acc[i] = 0.f;
    if (i < GG * 1024) g_S[i] = 0.f;
    if (i < GG * 32) g_m[i] = 0.f;
    if (i < M) { g_segcnt[i] = 0; g_cursor[i] = 0; }
}

// convert indices to int32 + histogram super_index in one pass
__global__ void k_cvthist(const void* nidx, const void* sidx, int N) {
    int i = blockIdx.x * blockDim.x + threadIdx.x;
    if (i >= N) return;
    int ni, si;
    if (g_is64) {
        ni = (int)((const long long*)nidx)[i];
        si = (int)((const long long*)sidx)[i];
    } else {
        ni = ((const int*)nidx)[i];
        si = ((const int*)sidx)[i];
    }
    g_ni[i] = ni;
    g_si[i] = si;
    atomicAdd(&g_segcnt[si], 1);
}

// ---------------------------------------------------------------------------
// Per-graph second moment S_g = x^T x (32x32) and mean vector m_g via tf32 mma.
// grid = (ceil(N/4096), GG); each block handles 4096 rows of ONE graph
// (ranges from binary search on sorted g_ni), so every block is uniform.
__global__ __launch_bounds__(512) void k_xtx(const float* __restrict__ x, int N) {
    __shared__ uint32_t sX[128][40];   // [row][chan], stride 40 (conflict-free)
    __shared__ float sS[1024];
    __shared__ float sM[32];

    const int g = blockIdx.y;
    const int lo = lbound(N, g), hi = lbound(N, g + 1);
    const int base = lo + blockIdx.x * 4096;
    if (base >= hi) return;
    const int rows = min(4096, hi - base);

    const int tid = threadIdx.x;
    const int lane = tid & 31, wid = tid >> 5;

    for (int i = tid; i < 1024; i += 512) sS[i] = 0.f;
    if (tid < 32) sM[tid] = 0.f;

    float acc[2][4][4];
#pragma unroll
    for (int m = 0; m < 2; m++)
#pragma unroll
        for (int jf = 0; jf < 4; jf++)
#pragma unroll
            for (int q = 0; q < 4; q++) acc[m][jf][q] = 0.f;

    const int lr = tid >> 2;            // loader row within chunk
    const int c8 = (tid & 3) * 8;       // loader channel group
    float msum[8];
#pragma unroll
    for (int t = 0; t < 8; t++) msum[t] = 0.f;

    const int nchunks = (rows + 127) >> 7;
    for (int ch = 0; ch < nchunks; ch++) {
        __syncthreads();
        {
            float4 v0, v1;
            int r = ch * 128 + lr;
            if (r < rows) {
                v0 = *(const float4*)&x[(size_t)(base + r) * D0 + c8];
                v1 = *(const float4*)&x[(size_t)(base + r) * D0 + c8 + 4];
            } else {
                v0 = make_float4(0.f, 0.f, 0.f, 0.f);
                v1 = v0;
            }
            msum[0] += v0.x; msum[1] += v0.y; msum[2] += v0.z; msum[3] += v0.w;
            msum[4] += v1.x; msum[5] += v1.y; msum[6] += v1.z; msum[7] += v1.w;
            sX[lr][c8 + 0] = f2tf(v0.x); sX[lr][c8 + 1] = f2tf(v0.y);
            sX[lr][c8 + 2] = f2tf(v0.z); sX[lr][c8 + 3] = f2tf(v0.w);
            sX[lr][c8 + 4] = f2tf(v1.x); sX[lr][c8 + 5] = f2tf(v1.y);
            sX[lr][c8 + 6] = f2tf(v1.z); sX[lr][c8 + 7] = f2tf(v1.w);
        }
        __syncthreads();

        // warp wid handles rows k = wid*8 .. wid*8+7 of this chunk
        const int k0 = wid * 8 + (lane & 3);
        uint32_t a[2][4];
#pragma unroll
        for (int m = 0; m < 2; m++) {
            int i0 = (lane >> 2) + 16 * m;
            a[m][0] = sX[k0][i0];     a[m][1] = sX[k0][i0 + 8];
            a[m][2] = sX[k0 + 4][i0]; a[m][3] = sX[k0 + 4][i0 + 8];
        }
#pragma unroll
        for (int jf = 0; jf < 4; jf++) {
            int j0 = jf * 8 + (lane >> 2);
            uint32_t b[2] = { sX[k0][j0], sX[k0 + 4][j0] };
#pragma unroll
            for (int m = 0; m < 2; m++) mma_tf32(acc[m][jf], a[m], b);
        }
    }

    // reduce: fragment (i,j) mapping: q01 -> row i0, q23 -> i0+8; col 2*(lane&3)+(q&1)
#pragma unroll
    for (int m = 0; m < 2; m++)
#pragma unroll
        for (int jf = 0; jf < 4; jf++)
#pragma unroll
            for (int q = 0; q < 4; q++) {
                int i = (lane >> 2) + 16 * m + 8 * (q >> 1);
                int j = jf * 8 + 2 * (lane & 3) + (q & 1);
                atomicAdd(&sS[i * 32 + j], acc[m][jf][q]);
            }
#pragma unroll
    for (int t = 0; t < 8; t++) atomicAdd(&sM[c8 + t], msum[t]);
    __syncthreads();

    for (int e = tid; e < 1024; e += 512) atomicAdd(&g_S[g * 1024 + e], sS[e]);
    if (tid < 32) atomicAdd(&g_m[g * 32 + tid], sM[tid]);
}

// ---------------------------------------------------------------------------
// layer-1 scale/shift from analytic moments. grid = GG blocks x 128 threads.
__global__ void k_fin1(const float* __restrict__ W1, const float* __restrict__ b1,
                       const float* __restrict__ gamma, const float* __restrict__ beta,
                       int N)
{
    __shared__ float sS[1024];
    __shared__ float sM[32];
    __shared__ int s_cnt;
    const int g = blockIdx.x, c = threadIdx.x;
    for (int i = c; i < 1024; i += 128) sS[i] = g_S[g * 1024 + i];
    if (c < 32) sM[c] = g_m[g * 32 + c];
    if (c == 0) s_cnt = lbound(N, g + 1) - lbound(N, g);
    __syncthreads();

    float w[32];
#pragma unroll
    for (int k = 0; k < 32; k++) w[k] = W1[c * 32 + k];

    float dot = 0.f, quad = 0.f;
#pragma unroll 4
    for (int k = 0; k < 32; k++) {
        float t = 0.f;
#pragma unroll
        for (int l = 0; l < 32; l++) t += sS[k * 32 + l] * w[l];
        quad += w[k] * t;
        dot += w[k] * sM[k];
    }
    float cnt = (float)s_cnt;
    float bias = b1[c];
    float sum_h = dot + cnt * bias;
    float sumsq = quad + 2.f * bias * dot + cnt * bias * bias;
    float cc = fmaxf(cnt, 1.f);
    float mean = sum_h / cc;
    float var = fmaxf(sumsq / cc - mean * mean, 0.f);
    float s = gamma[c] * rsqrtf(var + EPS);
    g_scale1[g * D1 + c] = s;
    g_shift1[g * D1 + c] = beta[c] - mean * s;
}

// layer-2 scale/shift from accumulated stats. grid = GG x 64.
__global__ void k_fin2(const float* __restrict__ gamma, const float* __restrict__ beta, int N) {
    __shared__ int s_cnt;
    const int g = blockIdx.x, c = threadIdx.x;
    if (c == 0) s_cnt = lbound(N, g + 1) - lbound(N, g);
    __syncthreads();
    float cc = fmaxf((float)s_cnt, 1.f);
    float mean = g_acc[OFF_S2 + g * D2 + c] / cc;
    float var = fmaxf(g_acc[OFF_SS2 + g * D2 + c] / cc - mean * mean, 0.f);
    float s = gamma[c] * rsqrtf(var + EPS);
    g_scale2[g * D2 + c] = s;
    g_shift2[g * D2 + c] = beta[c] - mean * s;
}

// fast two-level scan, single block of 1024 threads
__global__ void k_scan(int M) {
    __shared__ int wsum[32];
    int tid = threadIdx.x, lane = tid & 31, w = tid >> 5;
    int per = (M + 1023) >> 10;
    int s = tid * per;
    int e = min(s + per, M);
    int sum = 0;
    for (int i = s; i < e; i++) sum += g_segcnt[i];
    int v = sum;
#pragma unroll
    for (int off = 1; off < 32; off <<= 1) {
        int t = __shfl_up_sync(0xffffffffu, v, off);
        if (lane >= off) v += t;
    }
    if (lane == 31) wsum[w] = v;
    __syncthreads();
    if (w == 0) {
        int t = wsum[lane];
#pragma unroll
        for (int off = 1; off < 32; off <<= 1) {
            int u = __shfl_up_sync(0xffffffffu, t, off);
            if (lane >= off) t += u;
        }
        wsum[lane] = t;
    }
    __syncthreads();
    int run = (w ? wsum[w - 1] : 0) + (v - sum);
    for (int i = s; i < e; i++) { g_segoff[i] = run; run += g_segcnt[i]; }
    if (e == M) g_segoff[M] = run;
}

__global__ void k_fill(int N) {
    int i = blockIdx.x * blockDim.x + threadIdx.x;
    if (i >= N) return;
    int s = g_si[i];
    int pos = g_segoff[s] + atomicAdd(&g_cursor[s], 1);
    g_perm[pos] = i;
}

// ---------------------------------------------------------------------------
// Fused: GEMM1 -> normalize+leaky into sH -> GEMM2 -> stats2 -> store h2.
// Permuted smem layouts (pos(k): pairs (k,k+4) adjacent) -> LDS.64 frag loads.
// Dynamic SMEM (bytes):
//   [0, 69632)       sH[128 rows][136]  (tf32 normalized h1, perm cols)
//   [69632, +40960)  phase1: sA[128][40] + sW1[128][40]; later sW2[64][136]
//   [110592, +512)   red2[128];  [111104, +512) sg[128]
constexpr int SH_BYTES   = 128 * 136 * 4;     // 69632
constexpr int PH1_BYTES  = 2 * 128 * 40 * 4;  // 40960 (>= sW2: 64*136*4=34816)
constexpr int FUSED_SMEM = SH_BYTES + PH1_BYTES + 512 + 512;  // 111616

__global__ __launch_bounds__(512) void k_fused(
    const float* __restrict__ x, const float* __restrict__ W1,
    const float* __restrict__ b1, const float* __restrict__ W2,
    const float* __restrict__ b2, int N)
{
    extern __shared__ unsigned char dsm[];
    uint32_t (*sH)[136]  = (uint32_t(*)[136])dsm;
    uint32_t (*sA)[40]   = (uint32_t(*)[40])(dsm + SH_BYTES);
    uint32_t (*sW1)[40]  = (uint32_t(*)[40])(dsm + SH_BYTES + 128 * 40 * 4);
    uint32_t (*sW2)[136] = (uint32_t(*)[136])(dsm + SH_BYTES);
    float* red2 = (float*)(dsm + SH_BYTES + PH1_BYTES);   // [128]
    int*   sg   = (int*)(dsm + SH_BYTES + PH1_BYTES + 512);

    const int tid = threadIdx.x;
    const int r0 = blockIdx.x * 128;
    const int nrows = min(128, N - r0);

    // load x -> sA, W1 -> sW1 with perm layout (STS.64 pairs)
    {
        int r = tid >> 2, c8 = (tid & 3) * 8;
        float4 v0, v1;
        if (r < nrows) {
            v0 = *(const float4*)&x[(size_t)(r0 + r) * D0 + c8];
            v1 = *(const float4*)&x[(size_t)(r0 + r) * D0 + c8 + 4];
        } else { v0 = make_float4(0.f,0.f,0.f,0.f); v1 = v0; }
        uint32_t p0[4] = { f2tf(v0.x), f2tf(v0.y), f2tf(v0.z), f2tf(v0.w) };
        uint32_t p1[4] = { f2tf(v1.x), f2tf(v1.y), f2tf(v1.z), f2tf(v1.w) };
#pragma unroll
        for (int t = 0; t < 4; t++)
            *(uint2*)&sA[r][c8 + 2 * t] = make_uint2(p0[t], p1[t]);

        float4 w0 = *(const float4*)&W1[(size_t)r * D0 + c8];
        float4 w1 = *(const float4*)&W1[(size_t)r * D0 + c8 + 4];
        uint32_t q0[4] = { f2tf(w0.x), f2tf(w0.y), f2tf(w0.z), f2tf(w0.w) };
        uint32_t q1[4] = { f2tf(w1.x), f2tf(w1.y), f2tf(w1.z), f2tf(w1.w) };
#pragma unroll
        for (int t = 0; t < 4; t++)
            *(uint2*)&sW1[r][c8 + 2 * t] = make_uint2(q0[t], q1[t]);
    }
    if (tid < 128) { sg[tid] = (tid < nrows) ? g_ni[r0 + tid] : 0; red2[tid] = 0.f; }
    __syncthreads();

    const int lane = tid & 31, wid = tid >> 5;
    const int rb0 = (wid >> 1) * 16, cb = (wid & 1) * 64;
    const int r1 = rb0 + (lane >> 2), r2 = r1 + 8;

    float acc[8][4];
#pragma unroll
    for (int nf = 0; nf < 8; nf++)
#pragma unroll
        for (int q = 0; q < 4; q++) acc[nf][q] = 0.f;

    // GEMM1 mainloop: all fragment loads are LDS.64
#pragma unroll
    for (int ks = 0; ks < 4; ks++) {
        const int kp = ks * 8 + 2 * (lane & 3);
        uint2 pa = *(const uint2*)&sA[r1][kp];
        uint2 pb = *(const uint2*)&sA[r2][kp];
        uint32_t a[4] = { pa.x, pb.x, pa.y, pb.y };
#pragma unroll
        for (int nf = 0; nf < 8; nf++) {
            const int cn = cb + nf * 8 + (lane >> 2);
            uint2 bb = *(const uint2*)&sW1[cn][kp];
            uint32_t b[2] = { bb.x, bb.y };
            mma_tf32(acc[nf], a, b);
        }
    }
    __syncthreads();   // done reading sA/sW1; region becomes sW2

    const int g0 = sg[0];
    const bool uniform = (sg[nrows - 1] == g0);

    // normalize + leaky -> sH (perm cols; bias folded into shift)
    if (uniform) {
        const float* scp = &g_scale1[g0 * D1];
        const float* shp = &g_shift1[g0 * D1];
#pragma unroll
        for (int nf = 0; nf < 8; nf++)
#pragma unroll
            for (int j = 0; j < 2; j++) {
                int c = cb + nf * 8 + 2 * (lane & 3) + j;
                float sc = __ldg(&scp[c]);
                float sh = __ldg(&b1[c]) * sc + __ldg(&shp[c]);
                float t1 = acc[nf][j] * sc + sh;
                float t2 = acc[nf][j + 2] * sc + sh;
                int cp = kperm(c);
                sH[r1][cp] = f2tf(fmaxf(t1, SLOPE * t1));
                sH[r2][cp] = f2tf(fmaxf(t2, SLOPE * t2));
            }
    } else {
        int gA = sg[r1], gB = sg[r2];
#pragma unroll
        for (int nf = 0; nf < 8; nf++)
#pragma unroll
            for (int j = 0; j < 2; j++) {
                int c = cb + nf * 8 + 2 * (lane & 3) + j;
                float bias = __ldg(&b1[c]);
                float s1v = g_scale1[gA * D1 + c], h1v = g_shift1[gA * D1 + c];
                float s2v = g_scale1[gB * D1 + c], h2v = g_shift1[gB * D1 + c];
                float t1 = (acc[nf][j] + bias) * s1v + h1v;
                float t2 = (acc[nf][j + 2] + bias) * s2v + h2v;
                int cp = kperm(c);
                sH[r1][cp] = f2tf(fmaxf(t1, SLOPE * t1));
                sH[r2][cp] = f2tf(fmaxf(t2, SLOPE * t2));
            }
    }

    // load W2 [64,128] -> sW2 perm layout
    for (int i = tid; i < 1024; i += 512) {
        int c = i >> 4, c8 = (i & 15) * 8;
        float4 w0 = *(const float4*)&W2[(size_t)c * D1 + c8];
        float4 w1 = *(const float4*)&W2[(size_t)c * D1 + c8 + 4];
        uint32_t q0[4] = { f2tf(w0.x), f2tf(w0.y), f2tf(w0.z), f2tf(w0.w) };
        uint32_t q1[4] = { f2tf(w1.x), f2tf(w1.y), f2tf(w1.z), f2tf(w1.w) };
#pragma unroll
        for (int t = 0; t < 4; t++)
            *(uint2*)&sW2[c][c8 + 2 * t] = make_uint2(q0[t], q1[t]);
    }
    __syncthreads();

    // GEMM2: warp tile 16 rows x 32 cols, K=128; LDS.64 frag loads
    const int cb2 = (wid & 1) * 32;
    float acc2[4][4];
#pragma unroll
    for (int nf = 0; nf < 4; nf++)
#pragma unroll
        for (int q = 0; q < 4; q++) acc2[nf][q] = 0.f;

#pragma unroll
    for (int ks = 0; ks < 16; ks++) {
        const int kp = ks * 8 + 2 * (lane & 3);
        uint2 pa = *(const uint2*)&sH[r1][kp];
        uint2 pb = *(const uint2*)&sH[r2][kp];
        uint32_t a[4] = { pa.x, pb.x, pa.y, pb.y };
#pragma unroll
        for (int nf = 0; nf < 4; nf++) {
            const int cn = cb2 + nf * 8 + (lane >> 2);
            uint2 bb = *(const uint2*)&sW2[cn][kp];
            uint32_t b[2] = { bb.x, bb.y };
            mma_tf32(acc2[nf], a, b);
        }
    }

    // epilogue: bias, stats2, store raw h2
#pragma unroll
    for (int nf = 0; nf < 4; nf++) {
        int cpair = cb2 + nf * 8 + 2 * (lane & 3);
        float bias0 = __ldg(&b2[cpair]);
        float bias1 = __ldg(&b2[cpair + 1]);
        float h0a = acc2[nf][0] + bias0, h1a = acc2[nf][1] + bias1;
        float h0b = acc2[nf][2] + bias0, h1b = acc2[nf][3] + bias1;
        if (r1 < nrows) *(float2*)&g_h2[(size_t)(r0 + r1) * D2 + cpair] = make_float2(h0a, h1a);
        if (r2 < nrows) *(float2*)&g_h2[(size_t)(r0 + r2) * D2 + cpair] = make_float2(h0b, h1b);
        if (uniform) {
            float s0 = 0.f, ss0 = 0.f, s1 = 0.f, ss1 = 0.f;
            if (r1 < nrows) { s0 += h0a; ss0 += h0a * h0a; s1 += h1a; ss1 += h1a * h1a; }
            if (r2 < nrows) { s0 += h0b; ss0 += h0b * h0b; s1 += h1b; ss1 += h1b * h1b; }
#pragma unroll
            for (int off = 4; off < 32; off <<= 1) {
                s0  += __shfl_xor_sync(0xffffffffu, s0, off);
                ss0 += __shfl_xor_sync(0xffffffffu, ss0, off);
                s1  += __shfl_xor_sync(0xffffffffu, s1, off);
                ss1 += __shfl_xor_sync(0xffffffffu, ss1, off);
            }
            if (lane < 4) {
                atomicAdd(&red2[cpair], s0);
                atomicAdd(&red2[cpair + 1], s1);
                atomicAdd(&red2[64 + cpair], ss0);
                atomicAdd(&red2[64 + cpair + 1], ss1);
            }
        } else {
            if (r1 < nrows) {
                int g = sg[r1];
                atomicAdd(&g_acc[OFF_S2 + g * D2 + cpair], h0a);
                atomicAdd(&g_acc[OFF_SS2 + g * D2 + cpair], h0a * h0a);
                atomicAdd(&g_acc[OFF_S2 + g * D2 + cpair + 1], h1a);
                atomicAdd(&g_acc[OFF_SS2 + g * D2 + cpair + 1], h1a * h1a);
            }
            if (r2 < nrows) {
                int g = sg[r2];
                atomicAdd(&g_acc[OFF_S2 + g * D2 + cpair], h0b);
                atomicAdd(&g_acc[OFF_SS2 + g * D2 + cpair], h0b * h0b);
                atomicAdd(&g_acc[OFF_S2 + g * D2 + cpair + 1], h1b);
                atomicAdd(&g_acc[OFF_SS2 + g * D2 + cpair + 1], h1b * h1b);
            }
        }
    }

    if (uniform) {
        __syncthreads();
        if (tid < 64) {
            atomicAdd(&g_acc[OFF_S2 + g0 * D2 + tid], red2[tid]);
            atomicAdd(&g_acc[OFF_SS2 + g0 * D2 + tid], red2[64 + tid]);
        }
    }
}

// ---------------------------------------------------------------------------
// Gather-max: one warp per superpoint; lane handles channels (lane, lane+32).
__global__ void k_pool(float* __restrict__ out, int M) {
    int w = (blockIdx.x * blockDim.x + threadIdx.x) >> 5;
    int lane = threadIdx.x & 31;
    if (w >= M) return;
    int s = g_segoff[w], e = g_segoff[w + 1];
    float m0 = -3.402823466e38f, m1 = -3.402823466e38f;
    int row = (s < e) ? g_perm[s] : 0;
    for (int j = s; j < e; ++j) {
        int nrow = (j + 1 < e) ? g_perm[j + 1] : 0;
        int g = g_ni[row];
        size_t base = (size_t)row * D2;
        float v0 = g_h2[base + lane];
        float v1 = g_h2[base + 32 + lane];
        float a0 = v0 * g_scale2[g * D2 + lane] + g_shift2[g * D2 + lane];
        float a1 = v1 * g_scale2[g * D2 + 32 + lane] + g_shift2[g * D2 + 32 + lane];
        a0 = fmaxf(a0, SLOPE * a0);
        a1 = fmaxf(a1, SLOPE * a1);
        m0 = fmaxf(m0, a0);
        m1 = fmaxf(m1, a1);
        row = nrow;
    }
    if (s == e) { m0 = 0.f; m1 = 0.f; }
    out[(size_t)w * D2 + lane] = m0;
    out[(size_t)w * D2 + 32 + lane] = m1;
}

// ---------------------------------------------------------------------------
extern "C" void kernel_launch(void* const* d_in, const int* in_sizes, int n_in,
                              void* d_out, int out_size) {
    const float* x     = (const float*)d_in[0];
    const float* W1    = (const float*)d_in[1];
    const float* b1    = (const float*)d_in[2];
    const float* g1    = (const float*)d_in[3];
    const float* beta1 = (const float*)d_in[4];
    const float* W2    = (const float*)d_in[5];
    const float* b2    = (const float*)d_in[6];
    const float* g2    = (const float*)d_in[7];
    const float* beta2 = (const float*)d_in[8];
    const void*  nidx  = d_in[9];
    const void*  sidx  = d_in[10];
    float* out = (float*)d_out;

    int N = in_sizes[0] / D0;
    int M = out_size / D2;

    int zgrid = (max(M, GG * 1024) + 255) / 256;
    int ngrid = (N + 255) / 256;
    int tgrid = (N + 127) / 128;
    dim3 xgrid((N + 4095) / 4096, GG);

    cudaFuncSetAttribute(k_fused, cudaFuncAttributeMaxDynamicSharedMemorySize, FUSED_SMEM);

    k_detect<<<1, 32>>>(sidx, M);
    k_zero<<<zgrid, 256>>>(M);
    k_cvthist<<<ngrid, 256>>>(nidx, sidx, N);
    k_xtx<<<xgrid, 512>>>(x, N);
    k_fin1<<<GG, 128>>>(W1, b1, g1, beta1, N);
    k_fused<<<tgrid, 512, FUSED_SMEM>>>(x, W1, b1, W2, b2, N);
    k_fin2<<<GG, 64>>>(g2, beta2, N);
    k_scan<<<1, 1024>>>(M);
    k_fill<<<ngrid, 256>>>(N);
    k_pool<<<(M + 7) / 8, 256>>>(out, M);
}

// round 7
// speedup vs baseline: 2.2028x; 1.0124x over previous
#include <cuda_runtime.h>
#include <cstdint>

// ---------------------------------------------------------------------------
// NodeMLP: x[N,32] -> Linear(32,128) -> graphBN(G=16) -> LeakyReLU(0.01)
//          -> Linear(128,64) -> graphBN -> LeakyReLU -> segment_max into M
//
// R7: k_xtx double-buffered (hide DRAM latency behind MMA); k_fused W2
//     L2-prefetch + early smem staging. Analytic layer-1 stats retained.
// ---------------------------------------------------------------------------

constexpr int D0 = 32, D1 = 128, D2 = 64, GG = 16;
constexpr float EPS = 1e-5f;
constexpr float SLOPE = 0.01f;

constexpr size_t N_MAX = 1048576;
constexpr size_t M_MAX = 65536;

// layer-2 stats accumulators: [0,1024) sum, [1024,2048) sumsq  ([g][64])
constexpr int OFF_S2 = 0, OFF_SS2 = 1024, ACC_TOT = 2048;

__device__ float g_h2[N_MAX * (size_t)D2];   // raw (pre-norm) layer-2 output
__device__ float g_acc[ACC_TOT];
__device__ float g_S[GG * 1024];             // per-graph x^T x (32x32)
__device__ float g_m[GG * 32];               // per-graph sum x
__device__ float g_scale1[GG * D1], g_shift1[GG * D1];
__device__ float g_scale2[GG * D2], g_shift2[GG * D2];
__device__ int   g_ni[N_MAX], g_si[N_MAX], g_perm[N_MAX];
__device__ int   g_segcnt[M_MAX], g_segoff[M_MAX + 1], g_cursor[M_MAX];
__device__ int   g_is64;

// ---------------------------------------------------------------------------
__device__ __forceinline__ uint32_t f2tf(float f) {
    uint32_t u;
    asm("cvt.rna.tf32.f32 %0, %1;" : "=r"(u) : "f"(f));
    return u;
}

// D += A(16x8,row) * B(8x8,col)   tf32 in, fp32 accum
__device__ __forceinline__ void mma_tf32(float* d, const uint32_t* a, const uint32_t* b) {
    asm volatile(
        "mma.sync.aligned.m16n8k8.row.col.f32.tf32.tf32.f32 "
        "{%0,%1,%2,%3}, {%4,%5,%6,%7}, {%8,%9}, {%0,%1,%2,%3};"
        : "+f"(d[0]), "+f"(d[1]), "+f"(d[2]), "+f"(d[3])
        : "r"(a[0]), "r"(a[1]), "r"(a[2]), "r"(a[3]), "r"(b[0]), "r"(b[1]));
}

// permuted position of k within its 8-group: (k,k+4) become adjacent
__device__ __forceinline__ int kperm(int k) {
    return (k & ~7) | ((k & 3) << 1) | ((k >> 2) & 1);
}

// first index i in sorted g_ni[0..n) with g_ni[i] >= v
__device__ __forceinline__ int lbound(int n, int v) {
    int lo = 0, hi = n;
    while (lo < hi) {
        int mid = (lo + hi) >> 1;
        if (g_ni[mid] < v) lo = mid + 1; else hi = mid;
    }
    return lo;
}

// ---------------------------------------------------------------------------
__global__ void k_detect(const void* sidx, int M) {
    if (threadIdx.x == 0 && blockIdx.x == 0) {
        const long long* p = (const long long*)sidx;
        int ok64 = 1;
        for (int i = 0; i < 256; i++) {
            unsigned long long v = (unsigned long long)p[i];
            if (v >= (unsigned long long)M) { ok64 = 0; break; }
        }
        g_is64 = ok64;
    }
}

__global__ void k_zero(int M) {
    int i = blockIdx.x * blockDim.x + threadIdx.x;
    if (i < ACC_TOT) g_acc[i] = 0.f;
    if (i < GG * 1024) g_S[i] = 0.f;
    if (i < GG * 32) g_m[i] = 0.f;
    if (i < M) { g_segcnt[i] = 0; g_cursor[i] = 0; }
}

// convert indices to int32 + histogram super_index in one pass
__global__ void k_cvthist(const void* nidx, const void* sidx, int N) {
    int i = blockIdx.x * blockDim.x + threadIdx.x;
    if (i >= N) return;
    int ni, si;
    if (g_is64) {
        ni = (int)((const long long*)nidx)[i];
        si = (int)((const long long*)sidx)[i];
    } else {
        ni = ((const int*)nidx)[i];
        si = ((const int*)sidx)[i];
    }
    g_ni[i] = ni;
    g_si[i] = si;
    atomicAdd(&g_segcnt[si], 1);
}

// ---------------------------------------------------------------------------
// Per-graph second moment S_g = x^T x (32x32) and sum vector m_g via tf32 mma.
// Double-buffered: LDG for chunk ch+1 issued before MMAs on chunk ch.
__global__ __launch_bounds__(512) void k_xtx(const float* __restrict__ x, int N) {
    __shared__ uint32_t sX[2][128][40];   // [buf][row][chan]
    __shared__ float sS[1024];
    __shared__ float sM[32];

    const int g = blockIdx.y;
    const int lo = lbound(N, g), hi = lbound(N, g + 1);
    const int base = lo + blockIdx.x * 4096;
    if (base >= hi) return;
    const int rows = min(4096, hi - base);

    const int tid = threadIdx.x;
    const int lane = tid & 31, wid = tid >> 5;

    for (int i = tid; i < 1024; i += 512) sS[i] = 0.f;
    if (tid < 32) sM[tid] = 0.f;

    float acc[2][4][4];
#pragma unroll
    for (int m = 0; m < 2; m++)
#pragma unroll
        for (int jf = 0; jf < 4; jf++)
#pragma unroll
            for (int q = 0; q < 4; q++) acc[m][jf][q] = 0.f;

    const int lr = tid >> 2;            // loader row within chunk
    const int c8 = (tid & 3) * 8;       // loader channel group
    float msum[8];
#pragma unroll
    for (int t = 0; t < 8; t++) msum[t] = 0.f;

    const int nchunks = (rows + 127) >> 7;

    // prologue: load chunk 0 into buffer 0
    {
        float4 v0, v1;
        if (lr < rows) {
            v0 = *(const float4*)&x[(size_t)(base + lr) * D0 + c8];
            v1 = *(const float4*)&x[(size_t)(base + lr) * D0 + c8 + 4];
        } else { v0 = make_float4(0.f, 0.f, 0.f, 0.f); v1 = v0; }
        msum[0] += v0.x; msum[1] += v0.y; msum[2] += v0.z; msum[3] += v0.w;
        msum[4] += v1.x; msum[5] += v1.y; msum[6] += v1.z; msum[7] += v1.w;
        sX[0][lr][c8 + 0] = f2tf(v0.x); sX[0][lr][c8 + 1] = f2tf(v0.y);
        sX[0][lr][c8 + 2] = f2tf(v0.z); sX[0][lr][c8 + 3] = f2tf(v0.w);
        sX[0][lr][c8 + 4] = f2tf(v1.x); sX[0][lr][c8 + 5] = f2tf(v1.y);
        sX[0][lr][c8 + 6] = f2tf(v1.z); sX[0][lr][c8 + 7] = f2tf(v1.w);
    }
    __syncthreads();

    for (int ch = 0; ch < nchunks; ch++) {
        const uint32_t (*cur)[40] = sX[ch & 1];

        // issue next chunk's loads BEFORE consuming current (latency overlap)
        float4 n0, n1;
        const bool pending = (ch + 1 < nchunks);
        if (pending) {
            int r = (ch + 1) * 128 + lr;
            if (r < rows) {
                n0 = *(const float4*)&x[(size_t)(base + r) * D0 + c8];
                n1 = *(const float4*)&x[(size_t)(base + r) * D0 + c8 + 4];
            } else { n0 = make_float4(0.f, 0.f, 0.f, 0.f); n1 = n0; }
        }

        // warp wid handles k-rows wid*8 .. wid*8+7 of this chunk
        const int k0 = wid * 8 + (lane & 3);
        uint32_t a[2][4];
#pragma unroll
        for (int m = 0; m < 2; m++) {
            int i0 = (lane >> 2) + 16 * m;
            a[m][0] = cur[k0][i0];     a[m][1] = cur[k0][i0 + 8];
            a[m][2] = cur[k0 + 4][i0]; a[m][3] = cur[k0 + 4][i0 + 8];
        }
#pragma unroll
        for (int jf = 0; jf < 4; jf++) {
            int j0 = jf * 8 + (lane >> 2);
            uint32_t b[2] = { cur[k0][j0], cur[k0 + 4][j0] };
#pragma unroll
            for (int m = 0; m < 2; m++) mma_tf32(acc[m][jf], a[m], b);
        }

        if (pending) {
            uint32_t (*nxt)[40] = sX[(ch + 1) & 1];
            msum[0] += n0.x; msum[1] += n0.y; msum[2] += n0.z; msum[3] += n0.w;
            msum[4] += n1.x; msum[5] += n1.y; msum[6] += n1.z; msum[7] += n1.w;
            nxt[lr][c8 + 0] = f2tf(n0.x); nxt[lr][c8 + 1] = f2tf(n0.y);
            nxt[lr][c8 + 2] = f2tf(n0.z); nxt[lr][c8 + 3] = f2tf(n0.w);
            nxt[lr][c8 + 4] = f2tf(n1.x); nxt[lr][c8 + 5] = f2tf(n1.y);
            nxt[lr][c8 + 6] = f2tf(n1.z); nxt[lr][c8 + 7] = f2tf(n1.w);
        }
        __syncthreads();
    }

    // reduce fragments: row i = (lane>>2)+16m+8*(q>>1), col j = jf*8+2*(lane&3)+(q&1)
#pragma unroll
    for (int m = 0; m < 2; m++)
#pragma unroll
        for (int jf = 0; jf < 4; jf++)
#pragma unroll
            for (int q = 0; q < 4; q++) {
                int i = (lane >> 2) + 16 * m + 8 * (q >> 1);
                int j = jf * 8 + 2 * (lane & 3) + (q & 1);
                atomicAdd(&sS[i * 32 + j], acc[m][jf][q]);
            }
#pragma unroll
    for (int t = 0; t < 8; t++) atomicAdd(&sM[c8 + t], msum[t]);
    __syncthreads();

    for (int e = tid; e < 1024; e += 512) atomicAdd(&g_S[g * 1024 + e], sS[e]);
    if (tid < 32) atomicAdd(&g_m[g * 32 + tid], sM[tid]);
}

// ---------------------------------------------------------------------------
// layer-1 scale/shift from analytic moments. grid = GG blocks x 128 threads.
__global__ void k_fin1(const float* __restrict__ W1, const float* __restrict__ b1,
                       const float* __restrict__ gamma, const float* __restrict__ beta,
                       int N)
{
    __shared__ float sS[1024];
    __shared__ float sM[32];
    __shared__ int s_cnt;
    const int g = blockIdx.x, c = threadIdx.x;
    for (int i = c; i < 1024; i += 128) sS[i] = g_S[g * 1024 + i];
    if (c < 32) sM[c] = g_m[g * 32 + c];
    if (c == 0) s_cnt = lbound(N, g + 1) - lbound(N, g);
    __syncthreads();

    float w[32];
#pragma unroll
    for (int k = 0; k < 32; k++) w[k] = W1[c * 32 + k];

    float dot = 0.f, quad = 0.f;
#pragma unroll 4
    for (int k = 0; k < 32; k++) {
        float t = 0.f;
#pragma unroll
        for (int l = 0; l < 32; l++) t += sS[k * 32 + l] * w[l];
        quad += w[k] * t;
        dot += w[k] * sM[k];
    }
    float cnt = (float)s_cnt;
    float bias = b1[c];
    float sum_h = dot + cnt * bias;
    float sumsq = quad + 2.f * bias * dot + cnt * bias * bias;
    float cc = fmaxf(cnt, 1.f);
    float mean = sum_h / cc;
    float var = fmaxf(sumsq / cc - mean * mean, 0.f);
    float s = gamma[c] * rsqrtf(var + EPS);
    g_scale1[g * D1 + c] = s;
    g_shift1[g * D1 + c] = beta[c] - mean * s;
}

// layer-2 scale/shift from accumulated stats. grid = GG x 64.
__global__ void k_fin2(const float* __restrict__ gamma, const float* __restrict__ beta, int N) {
    __shared__ int s_cnt;
    const int g = blockIdx.x, c = threadIdx.x;
    if (c == 0) s_cnt = lbound(N, g + 1) - lbound(N, g);
    __syncthreads();
    float cc = fmaxf((float)s_cnt, 1.f);
    float mean = g_acc[OFF_S2 + g * D2 + c] / cc;
    float var = fmaxf(g_acc[OFF_SS2 + g * D2 + c] / cc - mean * mean, 0.f);
    float s = gamma[c] * rsqrtf(var + EPS);
    g_scale2[g * D2 + c] = s;
    g_shift2[g * D2 + c] = beta[c] - mean * s;
}

// fast two-level scan, single block of 1024 threads
__global__ void k_scan(int M) {
    __shared__ int wsum[32];
    int tid = threadIdx.x, lane = tid & 31, w = tid >> 5;
    int per = (M + 1023) >> 10;
    int s = tid * per;
    int e = min(s + per, M);
    int sum = 0;
    for (int i = s; i < e; i++) sum += g_segcnt[i];
    int v = sum;
#pragma unroll
    for (int off = 1; off < 32; off <<= 1) {
        int t = __shfl_up_sync(0xffffffffu, v, off);
        if (lane >= off) v += t;
    }
    if (lane == 31) wsum[w] = v;
    __syncthreads();
    if (w == 0) {
        int t = wsum[lane];
#pragma unroll
        for (int off = 1; off < 32; off <<= 1) {
            int u = __shfl_up_sync(0xffffffffu, t, off);
            if (lane >= off) t += u;
        }
        wsum[lane] = t;
    }
    __syncthreads();
    int run = (w ? wsum[w - 1] : 0) + (v - sum);
    for (int i = s; i < e; i++) { g_segoff[i] = run; run += g_segcnt[i]; }
    if (e == M) g_segoff[M] = run;
}

__global__ void k_fill(int N) {
    int i = blockIdx.x * blockDim.x + threadIdx.x;
    if (i >= N) return;
    int s = g_si[i];
    int pos = g_segoff[s] + atomicAdd(&g_cursor[s], 1);
    g_perm[pos] = i;
}

// ---------------------------------------------------------------------------
// Fused: GEMM1 -> normalize+leaky into sH -> GEMM2 -> stats2 -> store h2.
// Permuted smem layouts -> LDS.64 frag loads. W2 prefetched into L2 at start.
constexpr int SH_BYTES   = 128 * 136 * 4;     // 69632
constexpr int PH1_BYTES  = 2 * 128 * 40 * 4;  // 40960 (>= sW2: 64*136*4=34816)
constexpr int FUSED_SMEM = SH_BYTES + PH1_BYTES + 512 + 512;  // 111616

__global__ __launch_bounds__(512) void k_fused(
    const float* __restrict__ x, const float* __restrict__ W1,
    const float* __restrict__ b1, const float* __restrict__ W2,
    const float* __restrict__ b2, int N)
{
    extern __shared__ unsigned char dsm[];
    uint32_t (*sH)[136]  = (uint32_t(*)[136])dsm;
    uint32_t (*sA)[40]   = (uint32_t(*)[40])(dsm + SH_BYTES);
    uint32_t (*sW1)[40]  = (uint32_t(*)[40])(dsm + SH_BYTES + 128 * 40 * 4);
    uint32_t (*sW2)[136] = (uint32_t(*)[136])(dsm + SH_BYTES);
    float* red2 = (float*)(dsm + SH_BYTES + PH1_BYTES);   // [128]
    int*   sg   = (int*)(dsm + SH_BYTES + PH1_BYTES + 512);

    const int tid = threadIdx.x;
    const int r0 = blockIdx.x * 128;
    const int nrows = min(128, N - r0);

    // warm L2 with W2 (32KB): consumed after GEMM1
    if (tid < 256)
        asm volatile("prefetch.global.L2 [%0];" :: "l"(W2 + tid * 32));

    // load x -> sA, W1 -> sW1 with perm layout (STS.64 pairs)
    {
        int r = tid >> 2, c8 = (tid & 3) * 8;
        float4 v0, v1;
        if (r < nrows) {
            v0 = *(const float4*)&x[(size_t)(r0 + r) * D0 + c8];
            v1 = *(const float4*)&x[(size_t)(r0 + r) * D0 + c8 + 4];
        } else { v0 = make_float4(0.f,0.f,0.f,0.f); v1 = v0; }
        uint32_t p0[4] = { f2tf(v0.x), f2tf(v0.y), f2tf(v0.z), f2tf(v0.w) };
        uint32_t p1[4] = { f2tf(v1.x), f2tf(v1.y), f2tf(v1.z), f2tf(v1.w) };
#pragma unroll
        for (int t = 0; t < 4; t++)
            *(uint2*)&sA[r][c8 + 2 * t] = make_uint2(p0[t], p1[t]);

        float4 w0 = *(const float4*)&W1[(size_t)r * D0 + c8];
        float4 w1 = *(const float4*)&W1[(size_t)r * D0 + c8 + 4];
        uint32_t q0[4] = { f2tf(w0.x), f2tf(w0.y), f2tf(w0.z), f2tf(w0.w) };
        uint32_t q1[4] = { f2tf(w1.x), f2tf(w1.y), f2tf(w1.z), f2tf(w1.w) };
#pragma unroll
        for (int t = 0; t < 4; t++)
            *(uint2*)&sW1[r][c8 + 2 * t] = make_uint2(q0[t], q1[t]);
    }
    if (tid < 128) { sg[tid] = (tid < nrows) ? g_ni[r0 + tid] : 0; red2[tid] = 0.f; }
    __syncthreads();

    const int lane = tid & 31, wid = tid >> 5;
    const int rb0 = (wid >> 1) * 16, cb = (wid & 1) * 64;
    const int r1 = rb0 + (lane >> 2), r2 = r1 + 8;

    float acc[8][4];
#pragma unroll
    for (int nf = 0; nf < 8; nf++)
#pragma unroll
        for (int q = 0; q < 4; q++) acc[nf][q] = 0.f;

    // GEMM1 mainloop: all fragment loads are LDS.64
#pragma unroll
    for (int ks = 0; ks < 4; ks++) {
        const int kp = ks * 8 + 2 * (lane & 3);
        uint2 pa = *(const uint2*)&sA[r1][kp];
        uint2 pb = *(const uint2*)&sA[r2][kp];
        uint32_t a[4] = { pa.x, pb.x, pa.y, pb.y };
#pragma unroll
        for (int nf = 0; nf < 8; nf++) {
            const int cn = cb + nf * 8 + (lane >> 2);
            uint2 bb = *(const uint2*)&sW1[cn][kp];
            uint32_t b[2] = { bb.x, bb.y };
            mma_tf32(acc[nf], a, b);
        }
    }
    __syncthreads();   // done reading sA/sW1; region becomes sW2

    // stage W2 FIRST (L2-hit loads overlap the normalize math below)
    for (int i = tid; i < 1024; i += 512) {
        int c = i >> 4, c8 = (i & 15) * 8;
        float4 w0 = *(const float4*)&W2[(size_t)c * D1 + c8];
        float4 w1 = *(const float4*)&W2[(size_t)c * D1 + c8 + 4];
        uint32_t q0[4] = { f2tf(w0.x), f2tf(w0.y), f2tf(w0.z), f2tf(w0.w) };
        uint32_t q1[4] = { f2tf(w1.x), f2tf(w1.y), f2tf(w1.z), f2tf(w1.w) };
#pragma unroll
        for (int t = 0; t < 4; t++)
            *(uint2*)&sW2[c][c8 + 2 * t] = make_uint2(q0[t], q1[t]);
    }

    const int g0 = sg[0];
    const bool uniform = (sg[nrows - 1] == g0);

    // normalize + leaky -> sH (perm cols; bias folded into shift)
    if (uniform) {
        const float* scp = &g_scale1[g0 * D1];
        const float* shp = &g_shift1[g0 * D1];
#pragma unroll
        for (int nf = 0; nf < 8; nf++)
#pragma unroll
            for (int j = 0; j < 2; j++) {
                int c = cb + nf * 8 + 2 * (lane & 3) + j;
                float sc = __ldg(&scp[c]);
                float sh = __ldg(&b1[c]) * sc + __ldg(&shp[c]);
                float t1 = acc[nf][j] * sc + sh;
                float t2 = acc[nf][j + 2] * sc + sh;
                int cp = kperm(c);
                sH[r1][cp] = f2tf(fmaxf(t1, SLOPE * t1));
                sH[r2][cp] = f2tf(fmaxf(t2, SLOPE * t2));
            }
    } else {
        int gA = sg[r1], gB = sg[r2];
#pragma unroll
        for (int nf = 0; nf < 8; nf++)
#pragma unroll
            for (int j = 0; j < 2; j++) {
                int c = cb + nf * 8 + 2 * (lane & 3) + j;
                float bias = __ldg(&b1[c]);
                float s1v = g_scale1[gA * D1 + c], h1v = g_shift1[gA * D1 + c];
                float s2v = g_scale1[gB * D1 + c], h2v = g_shift1[gB * D1 + c];
                float t1 = (acc[nf][j] + bias) * s1v + h1v;
                float t2 = (acc[nf][j + 2] + bias) * s2v + h2v;
                int cp = kperm(c);
                sH[r1][cp] = f2tf(fmaxf(t1, SLOPE * t1));
                sH[r2][cp] = f2tf(fmaxf(t2, SLOPE * t2));
            }
    }
    __syncthreads();

    // GEMM2: warp tile 16 rows x 32 cols, K=128; LDS.64 frag loads
    const int cb2 = (wid & 1) * 32;
    float acc2[4][4];
#pragma unroll
    for (int nf = 0; nf < 4; nf++)
#pragma unroll
        for (int q = 0; q < 4; q++) acc2[nf][q] = 0.f;

#pragma unroll
    for (int ks = 0; ks < 16; ks++) {
        const int kp = ks * 8 + 2 * (lane & 3);
        uint2 pa = *(const uint2*)&sH[r1][kp];
        uint2 pb = *(const uint2*)&sH[r2][kp];
        uint32_t a[4] = { pa.x, pb.x, pa.y, pb.y };
#pragma unroll
        for (int nf = 0; nf < 4; nf++) {
            const int cn = cb2 + nf * 8 + (lane >> 2);
            uint2 bb = *(const uint2*)&sW2[cn][kp];
            uint32_t b[2] = { bb.x, bb.y };
            mma_tf32(acc2[nf], a, b);
        }
    }

    // epilogue: bias, stats2, store raw h2
#pragma unroll
    for (int nf = 0; nf < 4; nf++) {
        int cpair = cb2 + nf * 8 + 2 * (lane & 3);
        float bias0 = __ldg(&b2[cpair]);
        float bias1 = __ldg(&b2[cpair + 1]);
        float h0a = acc2[nf][0] + bias0, h1a = acc2[nf][1] + bias1;
        float h0b = acc2[nf][2] + bias0, h1b = acc2[nf][3] + bias1;
        if (r1 < nrows) *(float2*)&g_h2[(size_t)(r0 + r1) * D2 + cpair] = make_float2(h0a, h1a);
        if (r2 < nrows) *(float2*)&g_h2[(size_t)(r0 + r2) * D2 + cpair] = make_float2(h0b, h1b);
        if (uniform) {
            float s0 = 0.f, ss0 = 0.f, s1 = 0.f, ss1 = 0.f;
            if (r1 < nrows) { s0 += h0a; ss0 += h0a * h0a; s1 += h1a; ss1 += h1a * h1a; }
            if (r2 < nrows) { s0 += h0b; ss0 += h0b * h0b; s1 += h1b; ss1 += h1b * h1b; }
#pragma unroll
            for (int off = 4; off < 32; off <<= 1) {
                s0  += __shfl_xor_sync(0xffffffffu, s0, off);
                ss0 += __shfl_xor_sync(0xffffffffu, ss0, off);
                s1  += __shfl_xor_sync(0xffffffffu, s1, off);
                ss1 += __shfl_xor_sync(0xffffffffu, ss1, off);
            }
            if (lane < 4) {
                atomicAdd(&red2[cpair], s0);
                atomicAdd(&red2[cpair + 1], s1);
                atomicAdd(&red2[64 + cpair], ss0);
                atomicAdd(&red2[64 + cpair + 1], ss1);
            }
        } else {
            if (r1 < nrows) {
                int g = sg[r1];
                atomicAdd(&g_acc[OFF_S2 + g * D2 + cpair], h0a);
                atomicAdd(&g_acc[OFF_SS2 + g * D2 + cpair], h0a * h0a);
                atomicAdd(&g_acc[OFF_S2 + g * D2 + cpair + 1], h1a);
                atomicAdd(&g_acc[OFF_SS2 + g * D2 + cpair + 1], h1a * h1a);
            }
            if (r2 < nrows) {
                int g = sg[r2];
                atomicAdd(&g_acc[OFF_S2 + g * D2 + cpair], h0b);
                atomicAdd(&g_acc[OFF_SS2 + g * D2 + cpair], h0b * h0b);
                atomicAdd(&g_acc[OFF_S2 + g * D2 + cpair + 1], h1b);
                atomicAdd(&g_acc[OFF_SS2 + g * D2 + cpair + 1], h1b * h1b);
            }
        }
    }

    if (uniform) {
        __syncthreads();
        if (tid < 64) {
            atomicAdd(&g_acc[OFF_S2 + g0 * D2 + tid], red2[tid]);
            atomicAdd(&g_acc[OFF_SS2 + g0 * D2 + tid], red2[64 + tid]);
        }
    }
}

// ---------------------------------------------------------------------------
// Gather-max: one warp per superpoint; lane handles channels (lane, lane+32).
__global__ void k_pool(float* __restrict__ out, int M) {
    int w = (blockIdx.x * blockDim.x + threadIdx.x) >> 5;
    int lane = threadIdx.x & 31;
    if (w >= M) return;
    int s = g_segoff[w], e = g_segoff[w + 1];
    float m0 = -3.402823466e38f, m1 = -3.402823466e38f;
    int row = (s < e) ? g_perm[s] : 0;
    for (int j = s; j < e; ++j) {
        int nrow = (j + 1 < e) ? g_perm[j + 1] : 0;
        int g = g_ni[row];
        size_t base = (size_t)row * D2;
        float v0 = g_h2[base + lane];
        float v1 = g_h2[base + 32 + lane];
        float a0 = v0 * g_scale2[g * D2 + lane] + g_shift2[g * D2 + lane];
        float a1 = v1 * g_scale2[g * D2 + 32 + lane] + g_shift2[g * D2 + 32 + lane];
        a0 = fmaxf(a0, SLOPE * a0);
        a1 = fmaxf(a1, SLOPE * a1);
        m0 = fmaxf(m0, a0);
        m1 = fmaxf(m1, a1);
        row = nrow;
    }
    if (s == e) { m0 = 0.f; m1 = 0.f; }
    out[(size_t)w * D2 + lane] = m0;
    out[(size_t)w * D2 + 32 + lane] = m1;
}

// ---------------------------------------------------------------------------
extern "C" void kernel_launch(void* const* d_in, const int* in_sizes, int n_in,
                              void* d_out, int out_size) {
    const float* x     = (const float*)d_in[0];
    const float* W1    = (const float*)d_in[1];
    const float* b1    = (const float*)d_in[2];
    const float* g1    = (const float*)d_in[3];
    const float* beta1 = (const float*)d_in[4];
    const float* W2    = (const float*)d_in[5];
    const float* b2    = (const float*)d_in[6];
    const float* g2    = (const float*)d_in[7];
    const float* beta2 = (const float*)d_in[8];
    const void*  nidx  = d_in[9];
    const void*  sidx  = d_in[10];
    float* out = (float*)d_out;

    int N = in_sizes[0] / D0;
    int M = out_size / D2;

    int zgrid = (max(M, GG * 1024) + 255) / 256;
    int ngrid = (N + 255) / 256;
    int tgrid = (N + 127) / 128;
    dim3 xgrid((N + 4095) / 4096, GG);

    cudaFuncSetAttribute(k_fused, cudaFuncAttributeMaxDynamicSharedMemorySize, FUSED_SMEM);

    k_detect<<<1, 32>>>(sidx, M);
    k_zero<<<zgrid, 256>>>(M);
    k_cvthist<<<ngrid, 256>>>(nidx, sidx, N);
    k_xtx<<<xgrid, 512>>>(x, N);
    k_fin1<<<GG, 128>>>(W1, b1, g1, beta1, N);
    k_fused<<<tgrid, 512, FUSED_SMEM>>>(x, W1, b1, W2, b2, N);
    k_fin2<<<GG, 64>>>(g2, beta2, N);
    k_scan<<<1, 1024>>>(M);
    k_fill<<<ngrid, 256>>>(N);
    k_pool<<<(M + 7) / 8, 256>>>(out, M);
}

// round 8
// speedup vs baseline: 2.6361x; 1.1967x over previous
#include <cuda_runtime.h>
#include <cstdint>

// ---------------------------------------------------------------------------
// NodeMLP: x[N,32] -> Linear(32,128) -> graphBN(G=16) -> LeakyReLU(0.01)
//          -> Linear(128,64) -> graphBN -> LeakyReLU -> segment_max into M
//
// R8: k_xtx = 4-stage cp.async pipeline + ones-column (S and m in one MMA);
//     g_goff table (no per-block binary search); h2 written in CSR-permuted
//     order so k_pool streams sequentially.
// ---------------------------------------------------------------------------

constexpr int D0 = 32, D1 = 128, D2 = 64, GG = 16;
constexpr float EPS = 1e-5f;
constexpr float SLOPE = 0.01f;

constexpr size_t N_MAX = 1048576;
constexpr size_t M_MAX = 65536;

// layer-2 stats accumulators: [0,1024) sum, [1024,2048) sumsq  ([g][64])
constexpr int OFF_S2 = 0, OFF_SS2 = 1024, ACC_TOT = 2048;

__device__ float g_h2[N_MAX * (size_t)D2];   // raw h2, rows in CSR-permuted order
__device__ float g_acc[ACC_TOT];
__device__ float g_S[GG * 1024];             // per-graph x^T x (32x32)
__device__ float g_m[GG * 32];               // per-graph sum x
__device__ float g_scale1[GG * D1], g_shift1[GG * D1];
__device__ float g_scale2[GG * D2], g_shift2[GG * D2];
__device__ int   g_ni[N_MAX], g_si[N_MAX];
__device__ int   g_pos[N_MAX];               // node -> CSR slot
__device__ int   g_nip[N_MAX];               // CSR slot -> graph id
__device__ int   g_segcnt[M_MAX], g_segoff[M_MAX + 1], g_cursor[M_MAX];
__device__ int   g_goff[GG + 1];
__device__ int   g_is64;

// ---------------------------------------------------------------------------
__device__ __forceinline__ uint32_t f2tf(float f) {
    uint32_t u;
    asm("cvt.rna.tf32.f32 %0, %1;" : "=r"(u) : "f"(f));
    return u;
}

// D += A(16x8,row) * B(8x8,col)   tf32 in, fp32 accum
__device__ __forceinline__ void mma_tf32(float* d, const uint32_t* a, const uint32_t* b) {
    asm volatile(
        "mma.sync.aligned.m16n8k8.row.col.f32.tf32.tf32.f32 "
        "{%0,%1,%2,%3}, {%4,%5,%6,%7}, {%8,%9}, {%0,%1,%2,%3};"
        : "+f"(d[0]), "+f"(d[1]), "+f"(d[2]), "+f"(d[3])
        : "r"(a[0]), "r"(a[1]), "r"(a[2]), "r"(a[3]), "r"(b[0]), "r"(b[1]));
}

// permuted position of k within its 8-group: (k,k+4) become adjacent
__device__ __forceinline__ int kperm(int k) {
    return (k & ~7) | ((k & 3) << 1) | ((k >> 2) & 1);
}

// first index i in sorted g_ni[0..n) with g_ni[i] >= v
__device__ __forceinline__ int lbound(int n, int v) {
    int lo = 0, hi = n;
    while (lo < hi) {
        int mid = (lo + hi) >> 1;
        if (g_ni[mid] < v) lo = mid + 1; else hi = mid;
    }
    return lo;
}

// ---------------------------------------------------------------------------
// zero + detect (int64 vs int32 index width) merged
__global__ void k_zero(const void* sidx, int M) {
    int i = blockIdx.x * blockDim.x + threadIdx.x;
    if (i == 0) {
        const long long* p = (const long long*)sidx;
        int ok64 = 1;
        for (int t = 0; t < 256; t++) {
            unsigned long long v = (unsigned long long)p[t];
            if (v >= (unsigned long long)M) { ok64 = 0; break; }
        }
        g_is64 = ok64;
    }
    if (i < ACC_TOT) g_acc[i] = 0.f;
    if (i < GG * 1024) g_S[i] = 0.f;
    if (i < GG * 32) g_m[i] = 0.f;
    if (i < M) { g_segcnt[i] = 0; g_cursor[i] = 0; }
}

// convert indices to int32 + histogram super_index in one pass
__global__ void k_cvthist(const void* nidx, const void* sidx, int N) {
    int i = blockIdx.x * blockDim.x + threadIdx.x;
    if (i >= N) return;
    int ni, si;
    if (g_is64) {
        ni = (int)((const long long*)nidx)[i];
        si = (int)((const long long*)sidx)[i];
    } else {
        ni = ((const int*)nidx)[i];
        si = ((const int*)sidx)[i];
    }
    g_ni[i] = ni;
    g_si[i] = si;
    atomicAdd(&g_segcnt[si], 1);
}

// per-graph row ranges (norm_index is sorted)
__global__ void k_goff(int N) {
    int t = threadIdx.x;
    if (t <= GG) g_goff[t] = lbound(N, t);
}

// ---------------------------------------------------------------------------
// Per-graph moments via tf32 MMA with a 4-stage cp.async pipeline.
// A channel of constant 1.0 is appended (col 32) so S[i][32] = m[i].
constexpr int XTX_ROWS   = 2048;                       // rows per block
constexpr int XTX_STAGES = 4;
constexpr int XTX_STG_B  = 128 * 40 * 4;               // one stage: 128 rows x 40 cols
constexpr int XTX_SMEM   = XTX_STAGES * XTX_STG_B + 32 * 33 * 4;

__global__ __launch_bounds__(256) void k_xtx(const float* __restrict__ x, int N) {
    extern __shared__ unsigned char xsm[];
    uint32_t (*sX)[128][40] = (uint32_t(*)[128][40])xsm;
    float* sS = (float*)(xsm + XTX_STAGES * XTX_STG_B);   // [32][33]

    const int g = blockIdx.y;
    const int lo = g_goff[g], hi = g_goff[g + 1];
    const long long base = (long long)lo + (long long)blockIdx.x * XTX_ROWS;
    if (base >= hi) return;
    const int rows = min(XTX_ROWS, (int)(hi - base));
    const int nchunks = (rows + 127) >> 7;

    const int tid = threadIdx.x, lane = tid & 31, wid = tid >> 5;

    for (int i = tid; i < 32 * 33; i += 256) sS[i] = 0.f;
    // ones column (32) + zero pad (33..39), static for all stages
    for (int i = tid; i < XTX_STAGES * 128; i += 256) {
        int s = i >> 7, r = i & 127;
        sX[s][r][32] = 0x3f800000u;
#pragma unroll
        for (int c = 33; c < 40; c++) sX[s][r][c] = 0u;
    }
    __syncthreads();

    // loader: thread -> (row, 64B half-row), 4 x 16B cp.async each
    const int lrow = tid >> 1, lcol = (tid & 1) * 16;

#define XTX_ISSUE(CH) do {                                                    \
        int _r = (CH) * 128 + lrow;                                           \
        int _sz = (_r < rows) ? 16 : 0;                                       \
        const float* _src = x + (size_t)(base + min(_r, rows - 1)) * D0 + lcol; \
        uint32_t _dst = (uint32_t)__cvta_generic_to_shared(&sX[(CH) & 3][lrow][lcol]); \
        _Pragma("unroll")                                                     \
        for (int _i = 0; _i < 4; _i++)                                        \
            asm volatile("cp.async.ca.shared.global [%0], [%1], 16, %2;"      \
                         :: "r"(_dst + 16 * _i), "l"(_src + 4 * _i), "r"(_sz) \
                         : "memory");                                         \
    } while (0)

    for (int ch = 0; ch < 3; ch++) {
        if (ch < nchunks) XTX_ISSUE(ch);
        asm volatile("cp.async.commit_group;" ::: "memory");
    }

    float acc[2][5][4];
#pragma unroll
    for (int m = 0; m < 2; m++)
#pragma unroll
        for (int jf = 0; jf < 5; jf++)
#pragma unroll
            for (int q = 0; q < 4; q++) acc[m][jf][q] = 0.f;

    for (int ch = 0; ch < nchunks; ch++) {
        asm volatile("cp.async.wait_group 2;" ::: "memory");
        __syncthreads();
        // refill the stage consumed 3 iters ago (safe: sync above)
        if (ch + 3 < nchunks) XTX_ISSUE(ch + 3);
        asm volatile("cp.async.commit_group;" ::: "memory");

        const uint32_t (*cur)[40] = sX[ch & 3];
        // 8 warps x 2 halves cover the 128 contraction rows of this chunk
#pragma unroll
        for (int half = 0; half < 2; half++) {
            const int k0 = half * 64 + wid * 8 + (lane & 3);
            uint32_t a[2][4];
#pragma unroll
            for (int m = 0; m < 2; m++) {
                int i0 = (lane >> 2) + 16 * m;
                a[m][0] = cur[k0][i0];     a[m][1] = cur[k0][i0 + 8];
                a[m][2] = cur[k0 + 4][i0]; a[m][3] = cur[k0 + 4][i0 + 8];
            }
#pragma unroll
            for (int jf = 0; jf < 5; jf++) {
                int j0 = jf * 8 + (lane >> 2);
                uint32_t b[2] = { cur[k0][j0], cur[k0 + 4][j0] };
#pragma unroll
                for (int m = 0; m < 2; m++) mma_tf32(acc[m][jf], a[m], b);
            }
        }
    }
#undef XTX_ISSUE

    // reduce fragments: i = (lane>>2)+16m+8(q>>1), j = jf*8+2(lane&3)+(q&1)
#pragma unroll
    for (int m = 0; m < 2; m++)
#pragma unroll
        for (int jf = 0; jf < 5; jf++)
#pragma unroll
            for (int q = 0; q < 4; q++) {
                int i = (lane >> 2) + 16 * m + 8 * (q >> 1);
                int j = jf * 8 + 2 * (lane & 3) + (q & 1);
                if (j <= 32) atomicAdd(&sS[i * 33 + j], acc[m][jf][q]);
            }
    __syncthreads();

    for (int e = tid; e < 32 * 33; e += 256) {
        int i = e / 33, j = e % 33;
        if (j < 32) atomicAdd(&g_S[g * 1024 + i * 32 + j], sS[e]);
        else        atomicAdd(&g_m[g * 32 + i], sS[e]);
    }
}

// ---------------------------------------------------------------------------
// layer-1 scale/shift from analytic moments. grid = GG blocks x 128 threads.
__global__ void k_fin1(const float* __restrict__ W1, const float* __restrict__ b1,
                       const float* __restrict__ gamma, const float* __restrict__ beta,
                       int N)
{
    __shared__ float sS[1024];
    __shared__ float sM[32];
    const int g = blockIdx.x, c = threadIdx.x;
    for (int i = c; i < 1024; i += 128) sS[i] = g_S[g * 1024 + i];
    if (c < 32) sM[c] = g_m[g * 32 + c];
    __syncthreads();

    float w[32];
#pragma unroll
    for (int k = 0; k < 32; k++) w[k] = W1[c * 32 + k];

    float dot = 0.f, quad = 0.f;
#pragma unroll 4
    for (int k = 0; k < 32; k++) {
        float t = 0.f;
#pragma unroll
        for (int l = 0; l < 32; l++) t += sS[k * 32 + l] * w[l];
        quad += w[k] * t;
        dot += w[k] * sM[k];
    }
    float cnt = (float)(g_goff[g + 1] - g_goff[g]);
    float bias = b1[c];
    float sum_h = dot + cnt * bias;
    float sumsq = quad + 2.f * bias * dot + cnt * bias * bias;
    float cc = fmaxf(cnt, 1.f);
    float mean = sum_h / cc;
    float var = fmaxf(sumsq / cc - mean * mean, 0.f);
    float s = gamma[c] * rsqrtf(var + EPS);
    g_scale1[g * D1 + c] = s;
    g_shift1[g * D1 + c] = beta[c] - mean * s;
}

// layer-2 scale/shift from accumulated stats. grid = GG x 64.
__global__ void k_fin2(const float* __restrict__ gamma, const float* __restrict__ beta, int N) {
    const int g = blockIdx.x, c = threadIdx.x;
    float cc = fmaxf((float)(g_goff[g + 1] - g_goff[g]), 1.f);
    float mean = g_acc[OFF_S2 + g * D2 + c] / cc;
    float var = fmaxf(g_acc[OFF_SS2 + g * D2 + c] / cc - mean * mean, 0.f);
    float s = gamma[c] * rsqrtf(var + EPS);
    g_scale2[g * D2 + c] = s;
    g_shift2[g * D2 + c] = beta[c] - mean * s;
}

// fast two-level scan, single block of 1024 threads
__global__ void k_scan(int M) {
    __shared__ int wsum[32];
    int tid = threadIdx.x, lane = tid & 31, w = tid >> 5;
    int per = (M + 1023) >> 10;
    int s = tid * per;
    int e = min(s + per, M);
    int sum = 0;
    for (int i = s; i < e; i++) sum += g_segcnt[i];
    int v = sum;
#pragma unroll
    for (int off = 1; off < 32; off <<= 1) {
        int t = __shfl_up_sync(0xffffffffu, v, off);
        if (lane >= off) v += t;
    }
    if (lane == 31) wsum[w] = v;
    __syncthreads();
    if (w == 0) {
        int t = wsum[lane];
#pragma unroll
        for (int off = 1; off < 32; off <<= 1) {
            int u = __shfl_up_sync(0xffffffffu, t, off);
            if (lane >= off) t += u;
        }
        wsum[lane] = t;
    }
    __syncthreads();
    int run = (w ? wsum[w - 1] : 0) + (v - sum);
    for (int i = s; i < e; i++) { g_segoff[i] = run; run += g_segcnt[i]; }
    if (e == M) g_segoff[M] = run;
}

// CSR slot assignment: node i -> pos; also slot -> graph id for the pool
__global__ void k_fill(int N) {
    int i = blockIdx.x * blockDim.x + threadIdx.x;
    if (i >= N) return;
    int s = g_si[i];
    int pos = g_segoff[s] + atomicAdd(&g_cursor[s], 1);
    g_pos[i] = pos;
    g_nip[pos] = g_ni[i];
}

// ---------------------------------------------------------------------------
// Fused: GEMM1 -> normalize+leaky into sH -> GEMM2 -> stats2 -> scatter h2
// to CSR-permuted rows. Permuted smem layouts -> LDS.64 frag loads.
constexpr int SH_BYTES   = 128 * 136 * 4;     // 69632
constexpr int PH1_BYTES  = 2 * 128 * 40 * 4;  // 40960 (>= sW2: 64*136*4=34816)
constexpr int FUSED_SMEM = SH_BYTES + PH1_BYTES + 512 + 512;  // 111616

__global__ __launch_bounds__(512) void k_fused(
    const float* __restrict__ x, const float* __restrict__ W1,
    const float* __restrict__ b1, const float* __restrict__ W2,
    const float* __restrict__ b2, int N)
{
    extern __shared__ unsigned char dsm[];
    uint32_t (*sH)[136]  = (uint32_t(*)[136])dsm;
    uint32_t (*sA)[40]   = (uint32_t(*)[40])(dsm + SH_BYTES);
    uint32_t (*sW1)[40]  = (uint32_t(*)[40])(dsm + SH_BYTES + 128 * 40 * 4);
    uint32_t (*sW2)[136] = (uint32_t(*)[136])(dsm + SH_BYTES);
    float* red2 = (float*)(dsm + SH_BYTES + PH1_BYTES);   // [128]
    int*   sg   = (int*)(dsm + SH_BYTES + PH1_BYTES + 512);

    const int tid = threadIdx.x;
    const int r0 = blockIdx.x * 128;
    const int nrows = min(128, N - r0);

    const int lane = tid & 31, wid = tid >> 5;
    const int rb0 = (wid >> 1) * 16, cb = (wid & 1) * 64;
    const int r1 = rb0 + (lane >> 2), r2 = r1 + 8;

    // early loads: scatter positions for this thread's two rows
    int p1 = 0, p2 = 0;
    if (r1 < nrows) p1 = g_pos[r0 + r1];
    if (r2 < nrows) p2 = g_pos[r0 + r2];

    // warm L2 with W2 (32KB): consumed after GEMM1
    if (tid < 256)
        asm volatile("prefetch.global.L2 [%0];" :: "l"(W2 + tid * 32));

    // load x -> sA, W1 -> sW1 with perm layout (STS.64 pairs)
    {
        int r = tid >> 2, c8 = (tid & 3) * 8;
        float4 v0, v1;
        if (r < nrows) {
            v0 = *(const float4*)&x[(size_t)(r0 + r) * D0 + c8];
            v1 = *(const float4*)&x[(size_t)(r0 + r) * D0 + c8 + 4];
        } else { v0 = make_float4(0.f,0.f,0.f,0.f); v1 = v0; }
        uint32_t p0[4] = { f2tf(v0.x), f2tf(v0.y), f2tf(v0.z), f2tf(v0.w) };
        uint32_t pq[4] = { f2tf(v1.x), f2tf(v1.y), f2tf(v1.z), f2tf(v1.w) };
#pragma unroll
        for (int t = 0; t < 4; t++)
            *(uint2*)&sA[r][c8 + 2 * t] = make_uint2(p0[t], pq[t]);

        float4 w0 = *(const float4*)&W1[(size_t)r * D0 + c8];
        float4 w1 = *(const float4*)&W1[(size_t)r * D0 + c8 + 4];
        uint32_t q0[4] = { f2tf(w0.x), f2tf(w0.y), f2tf(w0.z), f2tf(w0.w) };
        uint32_t q1[4] = { f2tf(w1.x), f2tf(w1.y), f2tf(w1.z), f2tf(w1.w) };
#pragma unroll
        for (int t = 0; t < 4; t++)
            *(uint2*)&sW1[r][c8 + 2 * t] = make_uint2(q0[t], q1[t]);
    }
    if (tid < 128) { sg[tid] = (tid < nrows) ? g_ni[r0 + tid] : 0; red2[tid] = 0.f; }
    __syncthreads();

    float acc[8][4];
#pragma unroll
    for (int nf = 0; nf < 8; nf++)
#pragma unroll
        for (int q = 0; q < 4; q++) acc[nf][q] = 0.f;

    // GEMM1 mainloop: all fragment loads are LDS.64
#pragma unroll
    for (int ks = 0; ks < 4; ks++) {
        const int kp = ks * 8 + 2 * (lane & 3);
        uint2 pa = *(const uint2*)&sA[r1][kp];
        uint2 pb = *(const uint2*)&sA[r2][kp];
        uint32_t a[4] = { pa.x, pb.x, pa.y, pb.y };
#pragma unroll
        for (int nf = 0; nf < 8; nf++) {
            const int cn = cb + nf * 8 + (lane >> 2);
            uint2 bb = *(const uint2*)&sW1[cn][kp];
            uint32_t b[2] = { bb.x, bb.y };
            mma_tf32(acc[nf], a, b);
        }
    }
    __syncthreads();   // done reading sA/sW1; region becomes sW2

    // stage W2 FIRST (L2-hit loads overlap the normalize math below)
    for (int i = tid; i < 1024; i += 512) {
        int c = i >> 4, c8 = (i & 15) * 8;
        float4 w0 = *(const float4*)&W2[(size_t)c * D1 + c8];
        float4 w1 = *(const float4*)&W2[(size_t)c * D1 + c8 + 4];
        uint32_t q0[4] = { f2tf(w0.x), f2tf(w0.y), f2tf(w0.z), f2tf(w0.w) };
        uint32_t q1[4] = { f2tf(w1.x), f2tf(w1.y), f2tf(w1.z), f2tf(w1.w) };
#pragma unroll
        for (int t = 0; t < 4; t++)
            *(uint2*)&sW2[c][c8 + 2 * t] = make_uint2(q0[t], q1[t]);
    }

    const int g0 = sg[0];
    const bool uniform = (sg[nrows - 1] == g0);

    // normalize + leaky -> sH (perm cols; bias folded into shift)
    if (uniform) {
        const float* scp = &g_scale1[g0 * D1];
        const float* shp = &g_shift1[g0 * D1];
#pragma unroll
        for (int nf = 0; nf < 8; nf++)
#pragma unroll
            for (int j = 0; j < 2; j++) {
                int c = cb + nf * 8 + 2 * (lane & 3) + j;
                float sc = __ldg(&scp[c]);
                float sh = __ldg(&b1[c]) * sc + __ldg(&shp[c]);
                float t1 = acc[nf][j] * sc + sh;
                float t2 = acc[nf][j + 2] * sc + sh;
                int cp = kperm(c);
                sH[r1][cp] = f2tf(fmaxf(t1, SLOPE * t1));
                sH[r2][cp] = f2tf(fmaxf(t2, SLOPE * t2));
            }
    } else {
        int gA = sg[r1], gB = sg[r2];
#pragma unroll
        for (int nf = 0; nf < 8; nf++)
#pragma unroll
            for (int j = 0; j < 2; j++) {
                int c = cb + nf * 8 + 2 * (lane & 3) + j;
                float bias = __ldg(&b1[c]);
                float s1v = g_scale1[gA * D1 + c], h1v = g_shift1[gA * D1 + c];
                float s2v = g_scale1[gB * D1 + c], h2v = g_shift1[gB * D1 + c];
                float t1 = (acc[nf][j] + bias) * s1v + h1v;
                float t2 = (acc[nf][j + 2] + bias) * s2v + h2v;
                int cp = kperm(c);
                sH[r1][cp] = f2tf(fmaxf(t1, SLOPE * t1));
                sH[r2][cp] = f2tf(fmaxf(t2, SLOPE * t2));
            }
    }
    __syncthreads();

    // GEMM2: warp tile 16 rows x 32 cols, K=128; LDS.64 frag loads
    const int cb2 = (wid & 1) * 32;
    float acc2[4][4];
#pragma unroll
    for (int nf = 0; nf < 4; nf++)
#pragma unroll
        for (int q = 0; q < 4; q++) acc2[nf][q] = 0.f;

#pragma unroll
    for (int ks = 0; ks < 16; ks++) {
        const int kp = ks * 8 + 2 * (lane & 3);
        uint2 pa = *(const uint2*)&sH[r1][kp];
        uint2 pb = *(const uint2*)&sH[r2][kp];
        uint32_t a[4] = { pa.x, pb.x, pa.y, pb.y };
#pragma unroll
        for (int nf = 0; nf < 4; nf++) {
            const int cn = cb2 + nf * 8 + (lane >> 2);
            uint2 bb = *(const uint2*)&sW2[cn][kp];
            uint32_t b[2] = { bb.x, bb.y };
            mma_tf32(acc2[nf], a, b);
        }
    }

    // epilogue: bias, stats2, scatter raw h2 to CSR slots
#pragma unroll
    for (int nf = 0; nf < 4; nf++) {
        int cpair = cb2 + nf * 8 + 2 * (lane & 3);
        float bias0 = __ldg(&b2[cpair]);
        float bias1 = __ldg(&b2[cpair + 1]);
        float h0a = acc2[nf][0] + bias0, h1a = acc2[nf][1] + bias1;
        float h0b = acc2[nf][2] + bias0, h1b = acc2[nf][3] + bias1;
        if (r1 < nrows) *(float2*)&g_h2[(size_t)p1 * D2 + cpair] = make_float2(h0a, h1a);
        if (r2 < nrows) *(float2*)&g_h2[(size_t)p2 * D2 + cpair] = make_float2(h0b, h1b);
        if (uniform) {
            float s0 = 0.f, ss0 = 0.f, s1 = 0.f, ss1 = 0.f;
            if (r1 < nrows) { s0 += h0a; ss0 += h0a * h0a; s1 += h1a; ss1 += h1a * h1a; }
            if (r2 < nrows) { s0 += h0b; ss0 += h0b * h0b; s1 += h1b; ss1 += h1b * h1b; }
#pragma unroll
            for (int off = 4; off < 32; off <<= 1) {
                s0  += __shfl_xor_sync(0xffffffffu, s0, off);
                ss0 += __shfl_xor_sync(0xffffffffu, ss0, off);
                s1  += __shfl_xor_sync(0xffffffffu, s1, off);
                ss1 += __shfl_xor_sync(0xffffffffu, ss1, off);
            }
            if (lane < 4) {
                atomicAdd(&red2[cpair], s0);
                atomicAdd(&red2[cpair + 1], s1);
                atomicAdd(&red2[64 + cpair], ss0);
                atomicAdd(&red2[64 + cpair + 1], ss1);
            }
        } else {
            if (r1 < nrows) {
                int g = sg[r1];
                atomicAdd(&g_acc[OFF_S2 + g * D2 + cpair], h0a);
                atomicAdd(&g_acc[OFF_SS2 + g * D2 + cpair], h0a * h0a);
                atomicAdd(&g_acc[OFF_S2 + g * D2 + cpair + 1], h1a);
                atomicAdd(&g_acc[OFF_SS2 + g * D2 + cpair + 1], h1a * h1a);
            }
            if (r2 < nrows) {
                int g = sg[r2];
                atomicAdd(&g_acc[OFF_S2 + g * D2 + cpair], h0b);
                atomicAdd(&g_acc[OFF_SS2 + g * D2 + cpair], h0b * h0b);
                atomicAdd(&g_acc[OFF_S2 + g * D2 + cpair + 1], h1b);
                atomicAdd(&g_acc[OFF_SS2 + g * D2 + cpair + 1], h1b * h1b);
            }
        }
    }

    if (uniform) {
        __syncthreads();
        if (tid < 64) {
            atomicAdd(&g_acc[OFF_S2 + g0 * D2 + tid], red2[tid]);
            atomicAdd(&g_acc[OFF_SS2 + g0 * D2 + tid], red2[64 + tid]);
        }
    }
}

// ---------------------------------------------------------------------------
// Streaming gather-max: h2 rows are already in CSR order -> sequential reads.
__global__ void k_pool(float* __restrict__ out, int M) {
    int w = (blockIdx.x * blockDim.x + threadIdx.x) >> 5;
    int lane = threadIdx.x & 31;
    if (w >= M) return;
    int s = g_segoff[w], e = g_segoff[w + 1];
    float m0 = -3.402823466e38f, m1 = -3.402823466e38f;
    int g = (s < e) ? g_nip[s] : 0;
    for (int j = s; j < e; ++j) {
        int gn = (j + 1 < e) ? g_nip[j + 1] : 0;
        size_t base = (size_t)j * D2;
        float v0 = g_h2[base + lane];
        float v1 = g_h2[base + 32 + lane];
        float a0 = v0 * g_scale2[g * D2 + lane] + g_shift2[g * D2 + lane];
        float a1 = v1 * g_scale2[g * D2 + 32 + lane] + g_shift2[g * D2 + 32 + lane];
        a0 = fmaxf(a0, SLOPE * a0);
        a1 = fmaxf(a1, SLOPE * a1);
        m0 = fmaxf(m0, a0);
        m1 = fmaxf(m1, a1);
        g = gn;
    }
    if (s == e) { m0 = 0.f; m1 = 0.f; }
    out[(size_t)w * D2 + lane] = m0;
    out[(size_t)w * D2 + 32 + lane] = m1;
}

// ---------------------------------------------------------------------------
extern "C" void kernel_launch(void* const* d_in, const int* in_sizes, int n_in,
                              void* d_out, int out_size) {
    const float* x     = (const float*)d_in[0];
    const float* W1    = (const float*)d_in[1];
    const float* b1    = (const float*)d_in[2];
    const float* g1    = (const float*)d_in[3];
    const float* beta1 = (const float*)d_in[4];
    const float* W2    = (const float*)d_in[5];
    const float* b2    = (const float*)d_in[6];
    const float* g2    = (const float*)d_in[7];
    const float* beta2 = (const float*)d_in[8];
    const void*  nidx  = d_in[9];
    const void*  sidx  = d_in[10];
    float* out = (float*)d_out;

    int N = in_sizes[0] / D0;
    int M = out_size / D2;

    int zgrid = (max(M, GG * 1024) + 255) / 256;
    int ngrid = (N + 255) / 256;
    int tgrid = (N + 127) / 128;
    dim3 xgrid((N + XTX_ROWS - 1) / XTX_ROWS, GG);

    cudaFuncSetAttribute(k_fused, cudaFuncAttributeMaxDynamicSharedMemorySize, FUSED_SMEM);
    cudaFuncSetAttribute(k_xtx, cudaFuncAttributeMaxDynamicSharedMemorySize, XTX_SMEM);

    k_zero<<<zgrid, 256>>>(sidx, M);
    k_cvthist<<<ngrid, 256>>>(nidx, sidx, N);
    k_goff<<<1, 32>>>(N);
    k_xtx<<<xgrid, 256, XTX_SMEM>>>(x, N);        // 4th launch: profiled
    k_scan<<<1, 1024>>>(M);
    k_fill<<<ngrid, 256>>>(N);
    k_fin1<<<GG, 128>>>(W1, b1, g1, beta1, N);
    k_fused<<<tgrid, 512, FUSED_SMEM>>>(x, W1, b1, W2, b2, N);
    k_fin2<<<GG, 64>>>(g2, beta2, N);
    k_pool<<<(M + 7) / 8, 256>>>(out, M);
}